// round 2
// baseline (speedup 1.0000x reference)
#include <cuda_runtime.h>
#include <math.h>
#include <stdint.h>

// ---------------- scratch (device globals; no allocation allowed) ----------------
__device__ float g_q[6291456];            // [B][H][N][DK] = 2*12*4096*64
__device__ float g_k[6291456];
__device__ float g_v[6291456];
__device__ float g_pos[1023 * 768];       // positional features
__device__ float g_relk[12 * 1023 * 64];  // [H][2W-1][DK]
__device__ float g_att[6291456];          // [B*N][768] pre-projection attention out

// ---------------- kernel 1: positional embedding ----------------
// grid 1023 blocks x 128 threads; gamma pdf in fp64 (log-space cancellation ~4e5 -> O(1))
// NOTE: xlogy(conc-1, 0) = (conc-1)*log(0) = -inf (conc-1 != 0) -> prob = 1e-8 for the
// dist=0 row -> gamma_feat = 1.0 for ALL features there (max-normalized).
__global__ void pos_embed_kernel() {
    int r = blockIdx.x;          // 0..1022, dist = r - 511
    int j = threadIdx.x;         // 0..127 feature within group
    float dist = (float)(r - 511);
    double p = fabs((double)dist);

    // exponential feature: half_life = 2^linspace(3, 9, 128)
    double hl = exp2(3.0 + (double)j * (6.0 / 127.0));
    float ef = (float)exp(-0.6931471805599453 / hl * p);

    // central mask: 2^(j+1) - 1 > pos
    float cw = exp2f((float)(j + 1)) - 1.0f;   // inf for j+1=128 -> always true (matches jax)
    float cm = (cw > (float)p) ? 1.0f : 0.0f;

    // gamma pdf: mean = 4(j+1), stddev = 2 -> conc = (mean/2)^2, rate = mean/4
    double mean = 4.0 * (double)(j + 1);
    double conc = (mean * 0.5) * (mean * 0.5);
    double rate = mean * 0.25;
    double lp = -rate * p - (lgamma(conc) - conc * log(rate));
    if (p > 0.0) lp += (conc - 1.0) * log(p);
    // xlogy semantics: conc-1 > 0, so pos==0 gives -inf -> exp -> 0
    double prob = ((p > 0.0) ? exp(lp) : 0.0) + 1e-8;

    __shared__ double red[128];
    red[j] = prob;
    __syncthreads();
    for (int o = 64; o > 0; o >>= 1) {
        if (j < o) red[j] = fmax(red[j], red[j + o]);
        __syncthreads();
    }
    float gf = (float)(prob / red[0]);

    float sg = (dist > 0.f) ? 1.f : ((dist < 0.f) ? -1.f : 0.f);
    float* row = g_pos + (size_t)r * 768;
    row[j]       = ef;
    row[128 + j] = cm;
    row[256 + j] = gf;
    row[384 + j] = sg * ef;
    row[512 + j] = sg * cm;
    row[640 + j] = sg * gf;
}

// ---------------- kernel 2: generic fp32 GEMM, 128x64x16 tile, 8x4/thread ----------------
// mode 0: QKV scatter  (A=x [8192,768], B=w_qkv [768,2304] -> g_q/g_k/g_v)
// mode 1: relk scatter (A=g_pos [1023,768], B=w_rel [768,768] -> g_relk[h][r][d])
// mode 2: out proj     (A=g_att [8192,768], B=w_out [768,768], +bias -> C=d_out)
__global__ __launch_bounds__(256) void gemm_kernel(
    const float* __restrict__ A, const float* __restrict__ B,
    float* __restrict__ C, const float* __restrict__ bias,
    int M, int N, int K, int mode)
{
    __shared__ float As[16][128];   // stored transposed: As[k][m]
    __shared__ float Bs[16][64];

    int tid = threadIdx.x;
    int n0 = blockIdx.x * 64;
    int m0 = blockIdx.y * 128;
    int ty = tid >> 4;              // 0..15 -> rows ty*8..ty*8+7
    int tx = tid & 15;              // cols tx*4..tx*4+3

    int am = tid >> 2;              // 0..63
    int ak = (tid & 3) << 2;        // 0,4,8,12
    int bk = tid >> 4;              // 0..15
    int bn = (tid & 15) << 2;

    float acc[8][4];
#pragma unroll
    for (int i = 0; i < 8; i++)
#pragma unroll
        for (int jj = 0; jj < 4; jj++) acc[i][jj] = 0.f;

    for (int kb = 0; kb < K; kb += 16) {
#pragma unroll
        for (int half = 0; half < 2; half++) {
            int m = am + half * 64;
            float4 av = make_float4(0.f, 0.f, 0.f, 0.f);
            if (m0 + m < M) av = *(const float4*)(A + (size_t)(m0 + m) * K + kb + ak);
            As[ak + 0][m] = av.x; As[ak + 1][m] = av.y;
            As[ak + 2][m] = av.z; As[ak + 3][m] = av.w;
        }
        *(float4*)&Bs[bk][bn] = *(const float4*)(B + (size_t)(kb + bk) * N + n0 + bn);
        __syncthreads();

#pragma unroll
        for (int k = 0; k < 16; k++) {
            float a[8], bb[4];
            *(float4*)&a[0] = *(const float4*)&As[k][ty * 8];
            *(float4*)&a[4] = *(const float4*)&As[k][ty * 8 + 4];
            *(float4*)&bb[0] = *(const float4*)&Bs[k][tx * 4];
#pragma unroll
            for (int i = 0; i < 8; i++)
#pragma unroll
                for (int jj = 0; jj < 4; jj++)
                    acc[i][jj] += a[i] * bb[jj];
        }
        __syncthreads();
    }

    // epilogue
#pragma unroll
    for (int i = 0; i < 8; i++) {
        int m = m0 + ty * 8 + i;
        if (m >= M) continue;
        if (mode == 2) {
            int c = n0 + tx * 4;
            float4 bv = *(const float4*)(bias + c);
            float4 rres = make_float4(acc[i][0] + bv.x, acc[i][1] + bv.y,
                                      acc[i][2] + bv.z, acc[i][3] + bv.w);
            *(float4*)(C + (size_t)m * N + c) = rres;
        } else if (mode == 0) {
            int bidx = m >> 12;
            int nn = m & 4095;
#pragma unroll
            for (int jj = 0; jj < 4; jj++) {
                int c = n0 + tx * 4 + jj;
                int hd = c / 3;
                int which = c - hd * 3;
                int h = hd >> 6, d = hd & 63;
                float* dst = (which == 0) ? g_q : ((which == 1) ? g_k : g_v);
                dst[(((size_t)(bidx * 12 + h)) * 4096 + nn) * 64 + d] = acc[i][jj];
            }
        } else {  // mode 1: relk
#pragma unroll
            for (int jj = 0; jj < 4; jj++) {
                int c = n0 + tx * 4 + jj;
                int h = c >> 6, d = c & 63;
                g_relk[((size_t)h * 1023 + m) * 64 + d] = acc[i][jj];
            }
        }
    }
}

// ---------------- kernel 3: fused window attention ----------------
// grid: 1536 blocks (192 windows x 8 t-tiles of 64 rows), 256 threads.
// smem: S[64][516] full logits row, qc/qp[64][68], buf[128][68] (k/relk/v union), rowsum[64]
#define S_STRIDE 516
#define SMEM_FLOATS (64 * 516 + 2 * 64 * 68 + 128 * 68 + 64)

__global__ __launch_bounds__(256) void attn_kernel(const float* __restrict__ rcb,
                                                   const float* __restrict__ rpb)
{
    extern __shared__ float sm[];
    float* S      = sm;                      // 64*516
    float* qc     = sm + 64 * 516;           // 64*68
    float* qp     = qc + 64 * 68;            // 64*68
    float* buf    = qp + 64 * 68;            // 128*68
    float* rowsum = buf + 128 * 68;          // 64

    int tid = threadIdx.x;
    int tt  = blockIdx.x & 7;
    int win = blockIdx.x >> 3;               // 0..191
    int b = win / 96;
    int rem = win - b * 96;
    int h = rem >> 3;
    int w = rem & 7;
    int t0 = tt << 6;

    size_t base = ((size_t)(b * 12 + h)) * 4096 + (size_t)w * 512;
    const float* qb = g_q + (base + t0) * 64;
    const float* kb = g_k + base * 64;
    const float* vb = g_v + base * 64;
    const float* rb = g_relk + (size_t)h * 1023 * 64;

    int ty = tid >> 4, tx = tid & 15;

    // load q + biases
    {
        int r = tid >> 2;
        int c0 = (tid & 3) << 4;
        const float* qr = qb + r * 64 + c0;
        const float* bc = rcb + h * 64 + c0;
        const float* bp = rpb + h * 64 + c0;
        float* dc = qc + r * 68 + c0;
        float* dp = qp + r * 68 + c0;
#pragma unroll
        for (int i = 0; i < 4; i++) {
            float4 qv = *(const float4*)(qr + i * 4);
            float4 v1 = *(const float4*)(bc + i * 4);
            float4 v2 = *(const float4*)(bp + i * 4);
            *(float4*)(dc + i * 4) = make_float4(qv.x + v1.x, qv.y + v1.y, qv.z + v1.z, qv.w + v1.w);
            *(float4*)(dp + i * 4) = make_float4(qv.x + v2.x, qv.y + v2.y, qv.z + v2.z, qv.w + v2.w);
        }
    }

    // ---- content logits: 8 chunks of K[64x64] ----
    for (int sc = 0; sc < 8; sc++) {
        __syncthreads();
        {
            int r = tid >> 2;
            int c0 = (tid & 3) << 4;
            const float* src = kb + ((size_t)(sc * 64 + r)) * 64 + c0;
            float* dst = buf + r * 68 + c0;
#pragma unroll
            for (int i = 0; i < 4; i++) *(float4*)(dst + i * 4) = *(const float4*)(src + i * 4);
        }
        __syncthreads();

        float acc[4][4];
#pragma unroll
        for (int i = 0; i < 4; i++)
#pragma unroll
            for (int jj = 0; jj < 4; jj++) acc[i][jj] = 0.f;

#pragma unroll 4
        for (int d = 0; d < 64; d += 4) {
            float a[4][4], bv[4][4];
#pragma unroll
            for (int i = 0; i < 4; i++)  *(float4*)a[i]  = *(const float4*)&qc[(ty * 4 + i) * 68 + d];
#pragma unroll
            for (int jj = 0; jj < 4; jj++) *(float4*)bv[jj] = *(const float4*)&buf[(tx + 16 * jj) * 68 + d];
#pragma unroll
            for (int i = 0; i < 4; i++)
#pragma unroll
                for (int jj = 0; jj < 4; jj++)
#pragma unroll
                    for (int dd = 0; dd < 4; dd++)
                        acc[i][jj] += a[i][dd] * bv[jj][dd];
        }
#pragma unroll
        for (int i = 0; i < 4; i++)
#pragma unroll
            for (int jj = 0; jj < 4; jj++)
                S[(ty * 4 + i) * S_STRIDE + sc * 64 + tx + 16 * jj] = acc[i][jj] * 0.125f;
    }

    // ---- relative logits: R[t][rl] = qp . relk[rbase + rl], scatter S[t][rl + t - 63] += R ----
    int rbase = 448 - t0;   // r_global = rbase + rc*128 + rl ; s = rc*128 + rl + t_local - 63
    for (int rc = 0; rc < 5; rc++) {
        __syncthreads();
        {
            int r = tid >> 1;
            int c0 = (tid & 1) << 5;
            int rg = rbase + rc * 128 + r;
            if (rg > 1022) rg = 1022;   // clamped rows land at s>=512 and are skipped
            const float* src = rb + (size_t)rg * 64 + c0;
            float* dst = buf + r * 68 + c0;
#pragma unroll
            for (int i = 0; i < 8; i++) *(float4*)(dst + i * 4) = *(const float4*)(src + i * 4);
        }
        __syncthreads();

        float acc[4][8];
#pragma unroll
        for (int i = 0; i < 4; i++)
#pragma unroll
            for (int jj = 0; jj < 8; jj++) acc[i][jj] = 0.f;

#pragma unroll 2
        for (int d = 0; d < 64; d += 4) {
            float a[4][4], bv[8][4];
#pragma unroll
            for (int i = 0; i < 4; i++)  *(float4*)a[i]  = *(const float4*)&qp[(ty * 4 + i) * 68 + d];
#pragma unroll
            for (int jj = 0; jj < 8; jj++) *(float4*)bv[jj] = *(const float4*)&buf[(tx + 16 * jj) * 68 + d];
#pragma unroll
            for (int i = 0; i < 4; i++)
#pragma unroll
                for (int jj = 0; jj < 8; jj++)
#pragma unroll
                    for (int dd = 0; dd < 4; dd++)
                        acc[i][jj] += a[i][dd] * bv[jj][dd];
        }
#pragma unroll
        for (int i = 0; i < 4; i++) {
            int tl = ty * 4 + i;
#pragma unroll
            for (int jj = 0; jj < 8; jj++) {
                int s = rc * 128 + tx + 16 * jj + tl - 63;
                if (s >= 0 && s < 512) S[tl * S_STRIDE + s] += acc[i][jj];
            }
        }
    }
    __syncthreads();

    // ---- softmax (4 threads per row, conflict-free via stride 516) ----
    {
        int row = tid >> 2;
        int lane = tid & 3;
        float* Sr = S + row * S_STRIDE;
        float m = -3.0e38f;
        for (int s = lane; s < 512; s += 4) m = fmaxf(m, Sr[s]);
        m = fmaxf(m, __shfl_xor_sync(0xffffffffu, m, 1));
        m = fmaxf(m, __shfl_xor_sync(0xffffffffu, m, 2));
        float sum = 0.f;
        for (int s = lane; s < 512; s += 4) {
            float e = __expf(Sr[s] - m);
            Sr[s] = e;
            sum += e;
        }
        sum += __shfl_xor_sync(0xffffffffu, sum, 1);
        sum += __shfl_xor_sync(0xffffffffu, sum, 2);
        if (lane == 0) rowsum[row] = sum;
    }
    __syncthreads();

    // ---- P @ V over 8 v-chunks ----
    float o[4][4];
#pragma unroll
    for (int i = 0; i < 4; i++)
#pragma unroll
        for (int jj = 0; jj < 4; jj++) o[i][jj] = 0.f;

    for (int sc = 0; sc < 8; sc++) {
        __syncthreads();
        {
            int r = tid >> 2;
            int c0 = (tid & 3) << 4;
            const float* src = vb + ((size_t)(sc * 64 + r)) * 64 + c0;
            float* dst = buf + r * 68 + c0;
#pragma unroll
            for (int i = 0; i < 4; i++) *(float4*)(dst + i * 4) = *(const float4*)(src + i * 4);
        }
        __syncthreads();

#pragma unroll 4
        for (int s4 = 0; s4 < 64; s4 += 4) {
            float pr[4][4];
#pragma unroll
            for (int i = 0; i < 4; i++)
                *(float4*)pr[i] = *(const float4*)&S[(ty * 4 + i) * S_STRIDE + sc * 64 + s4];
#pragma unroll
            for (int ss = 0; ss < 4; ss++) {
                float bv[4];
                *(float4*)bv = *(const float4*)&buf[(s4 + ss) * 68 + tx * 4];
#pragma unroll
                for (int i = 0; i < 4; i++)
#pragma unroll
                    for (int jj = 0; jj < 4; jj++)
                        o[i][jj] += pr[i][ss] * bv[jj];
            }
        }
    }

    // ---- normalize + write [b*4096 + w*512 + t][h*64 + d] ----
#pragma unroll
    for (int i = 0; i < 4; i++) {
        float inv = 1.0f / rowsum[ty * 4 + i];
        size_t row = (size_t)b * 4096 + (size_t)w * 512 + t0 + ty * 4 + i;
        *(float4*)(g_att + row * 768 + h * 64 + tx * 4) =
            make_float4(o[i][0] * inv, o[i][1] * inv, o[i][2] * inv, o[i][3] * inv);
    }
}

// ---------------- launch ----------------
extern "C" void kernel_launch(void* const* d_in, const int* in_sizes, int n_in,
                              void* d_out, int out_size)
{
    const float* x     = (const float*)d_in[0];
    const float* w_qkv = (const float*)d_in[1];
    const float* w_out = (const float*)d_in[2];
    const float* b_out = (const float*)d_in[3];
    const float* w_rel = (const float*)d_in[4];
    const float* rcb   = (const float*)d_in[5];
    const float* rpb   = (const float*)d_in[6];
    float* out = (float*)d_out;

    cudaFuncSetAttribute(attn_kernel, cudaFuncAttributeMaxDynamicSharedMemorySize,
                         SMEM_FLOATS * (int)sizeof(float));

    float* pos_ptr; cudaGetSymbolAddress((void**)&pos_ptr, g_pos);
    float* att_ptr; cudaGetSymbolAddress((void**)&att_ptr, g_att);

    // 1. positional features
    pos_embed_kernel<<<1023, 128>>>();
    // 2. QKV projection: [8192,768] x [768,2304] -> scatter q/k/v
    gemm_kernel<<<dim3(36, 64), 256>>>(x, w_qkv, nullptr, nullptr, 8192, 2304, 768, 0);
    // 3. rel_k: [1023,768] x [768,768] -> g_relk[h][r][d]
    gemm_kernel<<<dim3(12, 8), 256>>>(pos_ptr, w_rel, nullptr, nullptr, 1023, 768, 768, 1);
    // 4. fused attention (192 windows x 8 row tiles)
    attn_kernel<<<1536, 256, SMEM_FLOATS * (int)sizeof(float)>>>(rcb, rpb);
    // 5. output projection + bias
    gemm_kernel<<<dim3(12, 64), 256>>>(att_ptr, w_out, out, b_out, 8192, 768, 768, 2);
}

// round 4
// speedup vs baseline: 1.4491x; 1.4491x over previous
#include <cuda_runtime.h>
#include <cuda_bf16.h>
#include <math.h>
#include <stdint.h>

// ================= scratch (device globals; zero-initialized at load) =================
__device__ float g_q[6291456];            // [B*H][4096][64]
__device__ float g_k[6291456];
__device__ float g_v[6291456];
__device__ float g_relk[12 * 1023 * 64];  // [H][2W-1][DK] fp32 (read by attn)

__device__ __nv_bfloat16 g_x_hi[8192 * 768],   g_x_lo[8192 * 768];
__device__ __nv_bfloat16 g_wqkv_hi[2304 * 768], g_wqkv_lo[2304 * 768];  // transposed [N][K]
__device__ __nv_bfloat16 g_wout_hi[768 * 768],  g_wout_lo[768 * 768];   // transposed
__device__ __nv_bfloat16 g_wrel_hi[768 * 768],  g_wrel_lo[768 * 768];   // transposed
__device__ __nv_bfloat16 g_pos_hi[1024 * 768],  g_pos_lo[1024 * 768];   // row 1023 stays zero (pad)
__device__ __nv_bfloat16 g_att_hi[8192 * 768],  g_att_lo[8192 * 768];

// ================= helpers =================
__device__ __forceinline__ uint32_t smem_u32(const void* p) {
    uint32_t a;
    asm("{ .reg .u64 t; cvta.to.shared.u64 t, %1; cvt.u32.u64 %0, t; }" : "=r"(a) : "l"(p));
    return a;
}
__device__ __forceinline__ void cp_async16(uint32_t dst, const void* src) {
    asm volatile("cp.async.ca.shared.global [%0], [%1], 16;" :: "r"(dst), "l"(src));
}
__device__ __forceinline__ void cp_commit() { asm volatile("cp.async.commit_group;"); }
__device__ __forceinline__ void cp_wait1() { asm volatile("cp.async.wait_group 1;"); }
__device__ __forceinline__ void cp_wait0() { asm volatile("cp.async.wait_group 0;"); }

__device__ __forceinline__ void ldsm4(uint32_t* r, uint32_t addr) {
    asm volatile("ldmatrix.sync.aligned.m8n8.x4.shared.b16 {%0,%1,%2,%3}, [%4];"
                 : "=r"(r[0]), "=r"(r[1]), "=r"(r[2]), "=r"(r[3]) : "r"(addr));
}
__device__ __forceinline__ void mma16816(float* d, const uint32_t* a, uint32_t b0, uint32_t b1) {
    asm volatile("mma.sync.aligned.m16n8k16.row.col.f32.bf16.bf16.f32 "
                 "{%0,%1,%2,%3}, {%4,%5,%6,%7}, {%8,%9}, {%0,%1,%2,%3};"
                 : "+f"(d[0]), "+f"(d[1]), "+f"(d[2]), "+f"(d[3])
                 : "r"(a[0]), "r"(a[1]), "r"(a[2]), "r"(a[3]), "r"(b0), "r"(b1));
}
__device__ __forceinline__ void split2(float v, __nv_bfloat16& h, __nv_bfloat16& l) {
    h = __float2bfloat16(v);
    l = __float2bfloat16(v - __bfloat162float(h));
}

// ================= kernel 1: positional embedding -> bf16 hi/lo =================
__global__ void pos_embed_kernel() {
    int r = blockIdx.x;          // 0..1022, dist = r - 511
    int j = threadIdx.x;         // 0..127
    float dist = (float)(r - 511);
    double p = fabs((double)dist);

    double hl = exp2(3.0 + (double)j * (6.0 / 127.0));
    float ef = (float)exp(-0.6931471805599453 / hl * p);

    float cw = exp2f((float)(j + 1)) - 1.0f;
    float cm = (cw > (float)p) ? 1.0f : 0.0f;

    double mean = 4.0 * (double)(j + 1);
    double conc = (mean * 0.5) * (mean * 0.5);
    double rate = mean * 0.25;
    double lp = -rate * p - (lgamma(conc) - conc * log(rate));
    if (p > 0.0) lp += (conc - 1.0) * log(p);
    double prob = ((p > 0.0) ? exp(lp) : 0.0) + 1e-8;  // xlogy(c-1,0) = -inf -> 0

    __shared__ double red[128];
    red[j] = prob;
    __syncthreads();
    for (int o = 64; o > 0; o >>= 1) {
        if (j < o) red[j] = fmax(red[j], red[j + o]);
        __syncthreads();
    }
    float gf = (float)(prob / red[0]);

    float sg = (dist > 0.f) ? 1.f : ((dist < 0.f) ? -1.f : 0.f);
    float vals[6] = {ef, cm, gf, sg * ef, sg * cm, sg * gf};
    size_t base = (size_t)r * 768;
#pragma unroll
    for (int s = 0; s < 6; s++) {
        __nv_bfloat16 h, l;
        split2(vals[s], h, l);
        g_pos_hi[base + s * 128 + j] = h;
        g_pos_lo[base + s * 128 + j] = l;
    }
}

// ================= split kernels =================
__global__ void split_kernel(const float* __restrict__ s, __nv_bfloat16* __restrict__ h,
                             __nv_bfloat16* __restrict__ l, int n) {
    int i = blockIdx.x * 256 + threadIdx.x;
    if (i < n) split2(s[i], h[i], l[i]);
}

// transpose + split: src [K][N] fp32 -> hi/lo [N][K] bf16
__global__ void splitT_kernel(const float* __restrict__ src, __nv_bfloat16* __restrict__ hi,
                              __nv_bfloat16* __restrict__ lo, int K, int N) {
    __shared__ float t[32][33];
    int n0 = blockIdx.x * 32, k0 = blockIdx.y * 32;
    int x = threadIdx.x, y0 = threadIdx.y;  // block 32x8
#pragma unroll
    for (int i = 0; i < 4; i++) {
        int y = y0 + i * 8;
        t[y][x] = src[(size_t)(k0 + y) * N + n0 + x];
    }
    __syncthreads();
#pragma unroll
    for (int i = 0; i < 4; i++) {
        int y = y0 + i * 8;
        float v = t[x][y];
        __nv_bfloat16 a, b;
        split2(v, a, b);
        size_t o = (size_t)(n0 + y) * K + k0 + x;
        hi[o] = a; lo[o] = b;
    }
}

// ================= kernel 2: mma.sync bf16x2-split GEMM =================
// C[M,N] = A[M,768] * B[N,768]^T. Block tile 128x96, 8 warps (4Mx2N), warp 32x48.
// K-chunks of 32, cp.async double-buffered. 3 products: AhBh + AhBl + AlBh.
// mode 0: QKV scatter; mode 1: relk scatter; mode 2: out-proj (+bias).
#define APB 10240            // A part bytes: 128 rows x 80B
#define BPB 7680             // B part bytes: 96 rows x 80B
#define STG 35840            // stage bytes: Ah Al Bh Bl
#define GEMM_SMEM (2 * STG)
#define S_ST 100             // fp32 staging stride

__global__ __launch_bounds__(256) void mma_gemm(
    const __nv_bfloat16* __restrict__ Ah, const __nv_bfloat16* __restrict__ Al,
    const __nv_bfloat16* __restrict__ Bh, const __nv_bfloat16* __restrict__ Bl,
    const float* __restrict__ bias, float* __restrict__ Cout, int mode)
{
    extern __shared__ char dsm[];
    uint32_t sbase = smem_u32(dsm);
    int tid = threadIdx.x, wid = tid >> 5, lane = tid & 31;
    int wm = wid & 3, wn = wid >> 2;

    size_t m0 = (size_t)blockIdx.y * 128;
    int n0 = blockIdx.x * 96;

    float acc[2][6][4];
#pragma unroll
    for (int i = 0; i < 2; i++)
#pragma unroll
        for (int j = 0; j < 6; j++)
#pragma unroll
            for (int q = 0; q < 4; q++) acc[i][j][q] = 0.f;

    // per-thread ldmatrix address components
    int a_lr = lane & 15;
    int a_lc = (lane >> 4) << 3;
    int b_ln = ((lane >> 4) << 3) + (lane & 7);
    int b_lk = lane & 8;

    // ---- cp.async fill of one stage ----
    auto fill = [&](int s, int c) {
        uint32_t st = sbase + s * STG;
        int k0 = c * 32;
#pragma unroll
        for (int ii = 0; ii < 7; ii++) {
            int i = tid + ii * 256;
            if (i < 1024) {
                int part = i >> 9, rr = (i >> 2) & 127, cc = i & 3;
                const __nv_bfloat16* src = (part ? Al : Ah) + (m0 + rr) * 768 + k0 + cc * 8;
                cp_async16(st + part * APB + rr * 80 + cc * 16, src);
            } else {
                int j = i - 1024;
                int part = j >= 384; int jj = j - (part ? 384 : 0);
                int rr = jj >> 2, cc = jj & 3;
                const __nv_bfloat16* src = (part ? Bl : Bh) + (size_t)(n0 + rr) * 768 + k0 + cc * 8;
                cp_async16(st + 2 * APB + part * BPB + rr * 80 + cc * 16, src);
            }
        }
        cp_commit();
    };

    fill(0, 0);
    for (int c = 0; c < 24; c++) {
        if (c < 23) { fill((c + 1) & 1, c + 1); cp_wait1(); } else { cp_wait0(); }
        __syncthreads();

        uint32_t st = sbase + (c & 1) * STG;
#pragma unroll
        for (int step = 0; step < 2; step++) {
            uint32_t ab = st + (wm * 32 + a_lr) * 80 + (step * 16 + a_lc) * 2;
            uint32_t bb = st + 2 * APB + (wn * 48 + b_ln) * 80 + (step * 16 + b_lk) * 2;
            uint32_t Af[2][4], Alf[2][4], Bf[3][4], Blf[3][4];
            ldsm4(Af[0], ab);           ldsm4(Af[1], ab + 1280);
            ldsm4(Alf[0], ab + APB);    ldsm4(Alf[1], ab + APB + 1280);
#pragma unroll
            for (int ng = 0; ng < 3; ng++) {
                ldsm4(Bf[ng],  bb + ng * 1280);
                ldsm4(Blf[ng], bb + BPB + ng * 1280);
            }
#pragma unroll
            for (int mi = 0; mi < 2; mi++)
#pragma unroll
                for (int ng = 0; ng < 3; ng++) {
                    mma16816(acc[mi][ng * 2 + 0], Af[mi],  Bf[ng][0],  Bf[ng][1]);
                    mma16816(acc[mi][ng * 2 + 0], Af[mi],  Blf[ng][0], Blf[ng][1]);
                    mma16816(acc[mi][ng * 2 + 0], Alf[mi], Bf[ng][0],  Bf[ng][1]);
                    mma16816(acc[mi][ng * 2 + 1], Af[mi],  Bf[ng][2],  Bf[ng][3]);
                    mma16816(acc[mi][ng * 2 + 1], Af[mi],  Blf[ng][2], Blf[ng][3]);
                    mma16816(acc[mi][ng * 2 + 1], Alf[mi], Bf[ng][2],  Bf[ng][3]);
                }
        }
        __syncthreads();
    }

    // ---- stage accumulators to smem S[128][100] ----
    float* S = (float*)dsm;
#pragma unroll
    for (int mi = 0; mi < 2; mi++)
#pragma unroll
        for (int nj = 0; nj < 6; nj++) {
            int row = wm * 32 + mi * 16 + (lane >> 2);
            int col = wn * 48 + nj * 8 + (lane & 3) * 2;
            S[row * S_ST + col]             = acc[mi][nj][0];
            S[row * S_ST + col + 1]         = acc[mi][nj][1];
            S[(row + 8) * S_ST + col]       = acc[mi][nj][2];
            S[(row + 8) * S_ST + col + 1]   = acc[mi][nj][3];
        }
    __syncthreads();

    // ---- coalesced scatter ----
    if (mode == 0) {
        // n-tile = head-half: h = bx/2, d base = 32*(bx&1); j = 3*ln + which
        int h = blockIdx.x >> 1;
        int dbase = (blockIdx.x & 1) * 32;
        int bi = (int)(m0 >> 12);
        int nn0 = (int)(m0 & 4095);
        float* bases[3] = {g_q + ((size_t)(bi * 12 + h) * 4096 + nn0) * 64 + dbase,
                           g_k + ((size_t)(bi * 12 + h) * 4096 + nn0) * 64 + dbase,
                           g_v + ((size_t)(bi * 12 + h) * 4096 + nn0) * 64 + dbase};
        for (int task = wid; task < 384; task += 8) {
            int mm = task / 3;
            int which = task - 3 * mm;
            bases[which][(size_t)mm * 64 + lane] = S[mm * S_ST + 3 * lane + which];
        }
    } else if (mode == 1) {
        for (int task = wid; task < 384; task += 8) {
            int mm = task / 3;
            int g = task - 3 * mm;
            int cgl = n0 + g * 32 + lane;
            int h = cgl >> 6, d = cgl & 63;
            int r = (int)m0 + mm;
            if (r < 1023)
                g_relk[((size_t)h * 1023 + r) * 64 + d] = S[mm * S_ST + g * 32 + lane];
        }
    } else {
        for (int task = wid; task < 384; task += 8) {
            int mm = task / 3;
            int g = task - 3 * mm;
            int j = g * 32 + lane;
            Cout[(m0 + mm) * 768 + n0 + j] = S[mm * S_ST + j] + bias[n0 + j];
        }
    }
}

// ================= kernel 3: fused window attention (SIMT, unchanged) =================
#define S_STRIDE 516
#define SMEM_FLOATS (64 * 516 + 2 * 64 * 68 + 128 * 68 + 64)

__global__ __launch_bounds__(256) void attn_kernel(const float* __restrict__ rcb,
                                                   const float* __restrict__ rpb)
{
    extern __shared__ float sm[];
    float* S      = sm;
    float* qc     = sm + 64 * 516;
    float* qp     = qc + 64 * 68;
    float* buf    = qp + 64 * 68;
    float* rowsum = buf + 128 * 68;

    int tid = threadIdx.x;
    int tt  = blockIdx.x & 7;
    int win = blockIdx.x >> 3;
    int b = win / 96;
    int rem = win - b * 96;
    int h = rem >> 3;
    int w = rem & 7;
    int t0 = tt << 6;

    size_t base = ((size_t)(b * 12 + h)) * 4096 + (size_t)w * 512;
    const float* qb = g_q + (base + t0) * 64;
    const float* kb = g_k + base * 64;
    const float* vb = g_v + base * 64;
    const float* rb = g_relk + (size_t)h * 1023 * 64;

    int ty = tid >> 4, tx = tid & 15;

    {
        int r = tid >> 2;
        int c0 = (tid & 3) << 4;
        const float* qr = qb + r * 64 + c0;
        const float* bc = rcb + h * 64 + c0;
        const float* bp = rpb + h * 64 + c0;
        float* dc = qc + r * 68 + c0;
        float* dp = qp + r * 68 + c0;
#pragma unroll
        for (int i = 0; i < 4; i++) {
            float4 qv = *(const float4*)(qr + i * 4);
            float4 v1 = *(const float4*)(bc + i * 4);
            float4 v2 = *(const float4*)(bp + i * 4);
            *(float4*)(dc + i * 4) = make_float4(qv.x + v1.x, qv.y + v1.y, qv.z + v1.z, qv.w + v1.w);
            *(float4*)(dp + i * 4) = make_float4(qv.x + v2.x, qv.y + v2.y, qv.z + v2.z, qv.w + v2.w);
        }
    }

    for (int sc = 0; sc < 8; sc++) {
        __syncthreads();
        {
            int r = tid >> 2;
            int c0 = (tid & 3) << 4;
            const float* src = kb + ((size_t)(sc * 64 + r)) * 64 + c0;
            float* dst = buf + r * 68 + c0;
#pragma unroll
            for (int i = 0; i < 4; i++) *(float4*)(dst + i * 4) = *(const float4*)(src + i * 4);
        }
        __syncthreads();

        float acc[4][4];
#pragma unroll
        for (int i = 0; i < 4; i++)
#pragma unroll
            for (int jj = 0; jj < 4; jj++) acc[i][jj] = 0.f;

#pragma unroll 4
        for (int d = 0; d < 64; d += 4) {
            float a[4][4], bv[4][4];
#pragma unroll
            for (int i = 0; i < 4; i++)  *(float4*)a[i]  = *(const float4*)&qc[(ty * 4 + i) * 68 + d];
#pragma unroll
            for (int jj = 0; jj < 4; jj++) *(float4*)bv[jj] = *(const float4*)&buf[(tx + 16 * jj) * 68 + d];
#pragma unroll
            for (int i = 0; i < 4; i++)
#pragma unroll
                for (int jj = 0; jj < 4; jj++)
#pragma unroll
                    for (int dd = 0; dd < 4; dd++)
                        acc[i][jj] += a[i][dd] * bv[jj][dd];
        }
#pragma unroll
        for (int i = 0; i < 4; i++)
#pragma unroll
            for (int jj = 0; jj < 4; jj++)
                S[(ty * 4 + i) * S_STRIDE + sc * 64 + tx + 16 * jj] = acc[i][jj] * 0.125f;
    }

    int rbase = 448 - t0;
    for (int rc = 0; rc < 5; rc++) {
        __syncthreads();
        {
            int r = tid >> 1;
            int c0 = (tid & 1) << 5;
            int rg = rbase + rc * 128 + r;
            if (rg > 1022) rg = 1022;
            const float* src = rb + (size_t)rg * 64 + c0;
            float* dst = buf + r * 68 + c0;
#pragma unroll
            for (int i = 0; i < 8; i++) *(float4*)(dst + i * 4) = *(const float4*)(src + i * 4);
        }
        __syncthreads();

        float acc[4][8];
#pragma unroll
        for (int i = 0; i < 4; i++)
#pragma unroll
            for (int jj = 0; jj < 8; jj++) acc[i][jj] = 0.f;

#pragma unroll 2
        for (int d = 0; d < 64; d += 4) {
            float a[4][4], bv[8][4];
#pragma unroll
            for (int i = 0; i < 4; i++)  *(float4*)a[i]  = *(const float4*)&qp[(ty * 4 + i) * 68 + d];
#pragma unroll
            for (int jj = 0; jj < 8; jj++) *(float4*)bv[jj] = *(const float4*)&buf[(tx + 16 * jj) * 68 + d];
#pragma unroll
            for (int i = 0; i < 4; i++)
#pragma unroll
                for (int jj = 0; jj < 8; jj++)
#pragma unroll
                    for (int dd = 0; dd < 4; dd++)
                        acc[i][jj] += a[i][dd] * bv[jj][dd];
        }
#pragma unroll
        for (int i = 0; i < 4; i++) {
            int tl = ty * 4 + i;
#pragma unroll
            for (int jj = 0; jj < 8; jj++) {
                int s = rc * 128 + tx + 16 * jj + tl - 63;
                if (s >= 0 && s < 512) S[tl * S_STRIDE + s] += acc[i][jj];
            }
        }
    }
    __syncthreads();

    {
        int row = tid >> 2;
        int lane = tid & 3;
        float* Sr = S + row * S_STRIDE;
        float m = -3.0e38f;
        for (int s = lane; s < 512; s += 4) m = fmaxf(m, Sr[s]);
        m = fmaxf(m, __shfl_xor_sync(0xffffffffu, m, 1));
        m = fmaxf(m, __shfl_xor_sync(0xffffffffu, m, 2));
        float sum = 0.f;
        for (int s = lane; s < 512; s += 4) {
            float e = __expf(Sr[s] - m);
            Sr[s] = e;
            sum += e;
        }
        sum += __shfl_xor_sync(0xffffffffu, sum, 1);
        sum += __shfl_xor_sync(0xffffffffu, sum, 2);
        if (lane == 0) rowsum[row] = sum;
    }
    __syncthreads();

    float o[4][4];
#pragma unroll
    for (int i = 0; i < 4; i++)
#pragma unroll
        for (int jj = 0; jj < 4; jj++) o[i][jj] = 0.f;

    for (int sc = 0; sc < 8; sc++) {
        __syncthreads();
        {
            int r = tid >> 2;
            int c0 = (tid & 3) << 4;
            const float* src = vb + ((size_t)(sc * 64 + r)) * 64 + c0;
            float* dst = buf + r * 68 + c0;
#pragma unroll
            for (int i = 0; i < 4; i++) *(float4*)(dst + i * 4) = *(const float4*)(src + i * 4);
        }
        __syncthreads();

#pragma unroll 4
        for (int s4 = 0; s4 < 64; s4 += 4) {
            float pr[4][4];
#pragma unroll
            for (int i = 0; i < 4; i++)
                *(float4*)pr[i] = *(const float4*)&S[(ty * 4 + i) * S_STRIDE + sc * 64 + s4];
#pragma unroll
            for (int ss = 0; ss < 4; ss++) {
                float bv[4];
                *(float4*)bv = *(const float4*)&buf[(s4 + ss) * 68 + tx * 4];
#pragma unroll
                for (int i = 0; i < 4; i++)
#pragma unroll
                    for (int jj = 0; jj < 4; jj++)
                        o[i][jj] += pr[i][ss] * bv[jj];
            }
        }
    }

    // normalize + write bf16 hi/lo (A operand of out-proj GEMM)
#pragma unroll
    for (int i = 0; i < 4; i++) {
        float inv = 1.0f / rowsum[ty * 4 + i];
        size_t row = (size_t)b * 4096 + (size_t)w * 512 + t0 + ty * 4 + i;
        size_t off = row * 768 + h * 64 + tx * 4;
        __nv_bfloat16 hh[4], ll[4];
#pragma unroll
        for (int jj = 0; jj < 4; jj++) split2(o[i][jj] * inv, hh[jj], ll[jj]);
        __nv_bfloat162 h01; h01.x = hh[0]; h01.y = hh[1];
        __nv_bfloat162 h23; h23.x = hh[2]; h23.y = hh[3];
        __nv_bfloat162 l01; l01.x = ll[0]; l01.y = ll[1];
        __nv_bfloat162 l23; l23.x = ll[2]; l23.y = ll[3];
        *(__nv_bfloat162*)(g_att_hi + off)     = h01;
        *(__nv_bfloat162*)(g_att_hi + off + 2) = h23;
        *(__nv_bfloat162*)(g_att_lo + off)     = l01;
        *(__nv_bfloat162*)(g_att_lo + off + 2) = l23;
    }
}

// ================= launch =================
extern "C" void kernel_launch(void* const* d_in, const int* in_sizes, int n_in,
                              void* d_out, int out_size)
{
    const float* x     = (const float*)d_in[0];
    const float* w_qkv = (const float*)d_in[1];
    const float* w_out = (const float*)d_in[2];
    const float* b_out = (const float*)d_in[3];
    const float* w_rel = (const float*)d_in[4];
    const float* rcb   = (const float*)d_in[5];
    const float* rpb   = (const float*)d_in[6];
    float* out = (float*)d_out;

    cudaFuncSetAttribute(attn_kernel, cudaFuncAttributeMaxDynamicSharedMemorySize,
                         SMEM_FLOATS * (int)sizeof(float));
    cudaFuncSetAttribute(mma_gemm, cudaFuncAttributeMaxDynamicSharedMemorySize, GEMM_SMEM);

    __nv_bfloat16 *xh, *xl, *qkvh, *qkvl, *outh, *outl, *relh, *rell, *posh, *posl, *atth, *attl;
    cudaGetSymbolAddress((void**)&xh, g_x_hi);     cudaGetSymbolAddress((void**)&xl, g_x_lo);
    cudaGetSymbolAddress((void**)&qkvh, g_wqkv_hi); cudaGetSymbolAddress((void**)&qkvl, g_wqkv_lo);
    cudaGetSymbolAddress((void**)&outh, g_wout_hi); cudaGetSymbolAddress((void**)&outl, g_wout_lo);
    cudaGetSymbolAddress((void**)&relh, g_wrel_hi); cudaGetSymbolAddress((void**)&rell, g_wrel_lo);
    cudaGetSymbolAddress((void**)&posh, g_pos_hi);  cudaGetSymbolAddress((void**)&posl, g_pos_lo);
    cudaGetSymbolAddress((void**)&atth, g_att_hi);  cudaGetSymbolAddress((void**)&attl, g_att_lo);

    // conversions + positional features
    pos_embed_kernel<<<1023, 128>>>();
    split_kernel<<<(6291456 + 255) / 256, 256>>>(x, xh, xl, 6291456);
    splitT_kernel<<<dim3(72, 24), dim3(32, 8)>>>(w_qkv, qkvh, qkvl, 768, 2304);
    splitT_kernel<<<dim3(24, 24), dim3(32, 8)>>>(w_out, outh, outl, 768, 768);
    splitT_kernel<<<dim3(24, 24), dim3(32, 8)>>>(w_rel, relh, rell, 768, 768);

    // QKV projection (tensor cores): [8192,768] x [2304,768]^T -> q/k/v scatter
    mma_gemm<<<dim3(24, 64), 256, GEMM_SMEM>>>(xh, xl, qkvh, qkvl, nullptr, nullptr, 0);
    // rel_k: [1024,768] x [768,768]^T -> g_relk
    mma_gemm<<<dim3(8, 8), 256, GEMM_SMEM>>>(posh, posl, relh, rell, nullptr, nullptr, 1);
    // fused attention
    attn_kernel<<<1536, 256, SMEM_FLOATS * (int)sizeof(float)>>>(rcb, rpb);
    // output projection: [8192,768] x [768,768]^T + bias -> out
    mma_gemm<<<dim3(8, 64), 256, GEMM_SMEM>>>(atth, attl, outh, outl, b_out, out, 2);
}

// round 5
// speedup vs baseline: 2.5555x; 1.7635x over previous
#include <cuda_runtime.h>
#include <cuda_bf16.h>
#include <math.h>
#include <stdint.h>

// ================= scratch (device globals) =================
__device__ float g_q[6291456];                         // [B*H][4096][64] fp32
__device__ __nv_bfloat16 g_k_hi[6291456], g_k_lo[6291456];
__device__ __nv_bfloat16 g_v_hi[6291456], g_v_lo[6291456];
__device__ __nv_bfloat16 g_relk_hi[12 * 1023 * 64], g_relk_lo[12 * 1023 * 64];

__device__ __nv_bfloat16 g_x_hi[8192 * 768],   g_x_lo[8192 * 768];
__device__ __nv_bfloat16 g_wqkv_hi[2304 * 768], g_wqkv_lo[2304 * 768];  // [N][K]
__device__ __nv_bfloat16 g_wout_hi[768 * 768],  g_wout_lo[768 * 768];
__device__ __nv_bfloat16 g_wrel_hi[768 * 768],  g_wrel_lo[768 * 768];
__device__ __nv_bfloat16 g_pos_hi[1024 * 768],  g_pos_lo[1024 * 768];
__device__ __nv_bfloat16 g_att_hi[8192 * 768],  g_att_lo[8192 * 768];

// ================= helpers =================
__device__ __forceinline__ uint32_t smem_u32(const void* p) {
    uint32_t a;
    asm("{ .reg .u64 t; cvta.to.shared.u64 t, %1; cvt.u32.u64 %0, t; }" : "=r"(a) : "l"(p));
    return a;
}
__device__ __forceinline__ void cp_async16(uint32_t dst, const void* src) {
    asm volatile("cp.async.ca.shared.global [%0], [%1], 16;" :: "r"(dst), "l"(src));
}
__device__ __forceinline__ void cp_commit() { asm volatile("cp.async.commit_group;"); }
__device__ __forceinline__ void cp_wait1() { asm volatile("cp.async.wait_group 1;"); }
__device__ __forceinline__ void cp_wait0() { asm volatile("cp.async.wait_group 0;"); }

__device__ __forceinline__ void ldsm4(uint32_t* r, uint32_t addr) {
    asm volatile("ldmatrix.sync.aligned.m8n8.x4.shared.b16 {%0,%1,%2,%3}, [%4];"
                 : "=r"(r[0]), "=r"(r[1]), "=r"(r[2]), "=r"(r[3]) : "r"(addr));
}
__device__ __forceinline__ void ldsm4t(uint32_t* r, uint32_t addr) {
    asm volatile("ldmatrix.sync.aligned.m8n8.x4.trans.shared.b16 {%0,%1,%2,%3}, [%4];"
                 : "=r"(r[0]), "=r"(r[1]), "=r"(r[2]), "=r"(r[3]) : "r"(addr));
}
__device__ __forceinline__ void mma16816(float* d, const uint32_t* a, uint32_t b0, uint32_t b1) {
    asm volatile("mma.sync.aligned.m16n8k16.row.col.f32.bf16.bf16.f32 "
                 "{%0,%1,%2,%3}, {%4,%5,%6,%7}, {%8,%9}, {%0,%1,%2,%3};"
                 : "+f"(d[0]), "+f"(d[1]), "+f"(d[2]), "+f"(d[3])
                 : "r"(a[0]), "r"(a[1]), "r"(a[2]), "r"(a[3]), "r"(b0), "r"(b1));
}
__device__ __forceinline__ void split2(float v, __nv_bfloat16& h, __nv_bfloat16& l) {
    h = __float2bfloat16(v);
    l = __float2bfloat16(v - __bfloat162float(h));
}
// pack (a,b) -> bf16x2 hi word (lo half = a); residual pair -> lo word
__device__ __forceinline__ uint32_t pack_split(float a, float b, uint32_t& lo) {
    uint32_t h;
    asm("cvt.rn.bf16x2.f32 %0, %1, %2;" : "=r"(h) : "f"(b), "f"(a));
    float ra = __uint_as_float(h << 16);
    float rb = __uint_as_float(h & 0xffff0000u);
    asm("cvt.rn.bf16x2.f32 %0, %1, %2;" : "=r"(lo) : "f"(b - rb), "f"(a - ra));
    return h;
}

// ================= kernel 1: positional embedding -> bf16 hi/lo =================
__global__ void pos_embed_kernel() {
    int r = blockIdx.x;          // dist = r - 511
    int j = threadIdx.x;
    float dist = (float)(r - 511);
    double p = fabs((double)dist);

    double hl = exp2(3.0 + (double)j * (6.0 / 127.0));
    float ef = (float)exp(-0.6931471805599453 / hl * p);

    float cw = exp2f((float)(j + 1)) - 1.0f;
    float cm = (cw > (float)p) ? 1.0f : 0.0f;

    double mean = 4.0 * (double)(j + 1);
    double conc = (mean * 0.5) * (mean * 0.5);
    double rate = mean * 0.25;
    double lp = -rate * p - (lgamma(conc) - conc * log(rate));
    if (p > 0.0) lp += (conc - 1.0) * log(p);
    double prob = ((p > 0.0) ? exp(lp) : 0.0) + 1e-8;  // xlogy(c-1,0) = -inf -> 0

    __shared__ double red[128];
    red[j] = prob;
    __syncthreads();
    for (int o = 64; o > 0; o >>= 1) {
        if (j < o) red[j] = fmax(red[j], red[j + o]);
        __syncthreads();
    }
    float gf = (float)(prob / red[0]);

    float sg = (dist > 0.f) ? 1.f : ((dist < 0.f) ? -1.f : 0.f);
    float vals[6] = {ef, cm, gf, sg * ef, sg * cm, sg * gf};
    size_t base = (size_t)r * 768;
#pragma unroll
    for (int s = 0; s < 6; s++) {
        __nv_bfloat16 h, l;
        split2(vals[s], h, l);
        g_pos_hi[base + s * 128 + j] = h;
        g_pos_lo[base + s * 128 + j] = l;
    }
}

// ================= split kernels =================
__global__ void split_kernel(const float* __restrict__ s, __nv_bfloat16* __restrict__ h,
                             __nv_bfloat16* __restrict__ l, int n) {
    int i = blockIdx.x * 256 + threadIdx.x;
    if (i < n) split2(s[i], h[i], l[i]);
}

__global__ void splitT_kernel(const float* __restrict__ src, __nv_bfloat16* __restrict__ hi,
                              __nv_bfloat16* __restrict__ lo, int K, int N) {
    __shared__ float t[32][33];
    int n0 = blockIdx.x * 32, k0 = blockIdx.y * 32;
    int x = threadIdx.x, y0 = threadIdx.y;
#pragma unroll
    for (int i = 0; i < 4; i++) {
        int y = y0 + i * 8;
        t[y][x] = src[(size_t)(k0 + y) * N + n0 + x];
    }
    __syncthreads();
#pragma unroll
    for (int i = 0; i < 4; i++) {
        int y = y0 + i * 8;
        float v = t[x][y];
        __nv_bfloat16 a, b;
        split2(v, a, b);
        size_t o = (size_t)(n0 + y) * K + k0 + x;
        hi[o] = a; lo[o] = b;
    }
}

// ================= kernel 2: mma.sync bf16x2-split GEMM =================
#define APB 10240
#define BPB 7680
#define STG 35840
#define GEMM_SMEM (2 * STG)
#define S_ST 100

__global__ __launch_bounds__(256) void mma_gemm(
    const __nv_bfloat16* __restrict__ Ah, const __nv_bfloat16* __restrict__ Al,
    const __nv_bfloat16* __restrict__ Bh, const __nv_bfloat16* __restrict__ Bl,
    const float* __restrict__ bias, float* __restrict__ Cout, int mode)
{
    extern __shared__ char dsm[];
    uint32_t sbase = smem_u32(dsm);
    int tid = threadIdx.x, wid = tid >> 5, lane = tid & 31;
    int wm = wid & 3, wn = wid >> 2;

    size_t m0 = (size_t)blockIdx.y * 128;
    int n0 = blockIdx.x * 96;

    float acc[2][6][4];
#pragma unroll
    for (int i = 0; i < 2; i++)
#pragma unroll
        for (int j = 0; j < 6; j++)
#pragma unroll
            for (int q = 0; q < 4; q++) acc[i][j][q] = 0.f;

    int a_lr = lane & 15;
    int a_lc = (lane >> 4) << 3;
    int b_ln = ((lane >> 4) << 3) + (lane & 7);
    int b_lk = lane & 8;

    auto fill = [&](int s, int c) {
        uint32_t st = sbase + s * STG;
        int k0 = c * 32;
#pragma unroll
        for (int ii = 0; ii < 7; ii++) {
            int i = tid + ii * 256;
            if (i < 1024) {
                int part = i >> 9, rr = (i >> 2) & 127, cc = i & 3;
                const __nv_bfloat16* src = (part ? Al : Ah) + (m0 + rr) * 768 + k0 + cc * 8;
                cp_async16(st + part * APB + rr * 80 + cc * 16, src);
            } else {
                int j = i - 1024;
                int part = j >= 384; int jj = j - (part ? 384 : 0);
                int rr = jj >> 2, cc = jj & 3;
                const __nv_bfloat16* src = (part ? Bl : Bh) + (size_t)(n0 + rr) * 768 + k0 + cc * 8;
                cp_async16(st + 2 * APB + part * BPB + rr * 80 + cc * 16, src);
            }
        }
        cp_commit();
    };

    fill(0, 0);
    for (int c = 0; c < 24; c++) {
        if (c < 23) { fill((c + 1) & 1, c + 1); cp_wait1(); } else { cp_wait0(); }
        __syncthreads();

        uint32_t st = sbase + (c & 1) * STG;
#pragma unroll
        for (int step = 0; step < 2; step++) {
            uint32_t ab = st + (wm * 32 + a_lr) * 80 + (step * 16 + a_lc) * 2;
            uint32_t bb = st + 2 * APB + (wn * 48 + b_ln) * 80 + (step * 16 + b_lk) * 2;
            uint32_t Af[2][4], Alf[2][4], Bf[3][4], Blf[3][4];
            ldsm4(Af[0], ab);           ldsm4(Af[1], ab + 1280);
            ldsm4(Alf[0], ab + APB);    ldsm4(Alf[1], ab + APB + 1280);
#pragma unroll
            for (int ng = 0; ng < 3; ng++) {
                ldsm4(Bf[ng],  bb + ng * 1280);
                ldsm4(Blf[ng], bb + BPB + ng * 1280);
            }
#pragma unroll
            for (int mi = 0; mi < 2; mi++)
#pragma unroll
                for (int ng = 0; ng < 3; ng++) {
                    mma16816(acc[mi][ng * 2 + 0], Af[mi],  Bf[ng][0],  Bf[ng][1]);
                    mma16816(acc[mi][ng * 2 + 0], Af[mi],  Blf[ng][0], Blf[ng][1]);
                    mma16816(acc[mi][ng * 2 + 0], Alf[mi], Bf[ng][0],  Bf[ng][1]);
                    mma16816(acc[mi][ng * 2 + 1], Af[mi],  Bf[ng][2],  Bf[ng][3]);
                    mma16816(acc[mi][ng * 2 + 1], Af[mi],  Blf[ng][2], Blf[ng][3]);
                    mma16816(acc[mi][ng * 2 + 1], Alf[mi], Bf[ng][2],  Bf[ng][3]);
                }
        }
        __syncthreads();
    }

    float* S = (float*)dsm;
#pragma unroll
    for (int mi = 0; mi < 2; mi++)
#pragma unroll
        for (int nj = 0; nj < 6; nj++) {
            int row = wm * 32 + mi * 16 + (lane >> 2);
            int col = wn * 48 + nj * 8 + (lane & 3) * 2;
            S[row * S_ST + col]             = acc[mi][nj][0];
            S[row * S_ST + col + 1]         = acc[mi][nj][1];
            S[(row + 8) * S_ST + col]       = acc[mi][nj][2];
            S[(row + 8) * S_ST + col + 1]   = acc[mi][nj][3];
        }
    __syncthreads();

    if (mode == 0) {
        int hh = blockIdx.x >> 1;
        int dbase = (blockIdx.x & 1) * 32;
        int bi = (int)(m0 >> 12);
        int nn0 = (int)(m0 & 4095);
        size_t ob = ((size_t)(bi * 12 + hh) * 4096 + nn0) * 64 + dbase;
        for (int task = wid; task < 384; task += 8) {
            int mm = task / 3;
            int which = task - 3 * mm;
            float v = S[mm * S_ST + 3 * lane + which];
            size_t o = ob + (size_t)mm * 64 + lane;
            if (which == 0) g_q[o] = v;
            else {
                __nv_bfloat16 hv, lv; split2(v, hv, lv);
                if (which == 1) { g_k_hi[o] = hv; g_k_lo[o] = lv; }
                else            { g_v_hi[o] = hv; g_v_lo[o] = lv; }
            }
        }
    } else if (mode == 1) {
        for (int task = wid; task < 384; task += 8) {
            int mm = task / 3;
            int g = task - 3 * mm;
            int cgl = n0 + g * 32 + lane;
            int hh = cgl >> 6, d = cgl & 63;
            int r = (int)m0 + mm;
            if (r < 1023) {
                __nv_bfloat16 hv, lv; split2(S[mm * S_ST + g * 32 + lane], hv, lv);
                size_t o = ((size_t)hh * 1023 + r) * 64 + d;
                g_relk_hi[o] = hv; g_relk_lo[o] = lv;
            }
        }
    } else {
        for (int task = wid; task < 384; task += 8) {
            int mm = task / 3;
            int g = task - 3 * mm;
            int j = g * 32 + lane;
            Cout[(m0 + mm) * 768 + n0 + j] = S[mm * S_ST + j] + bias[n0 + j];
        }
    }
}

// ================= kernel 3: tensor-core fused window attention =================
// block = 64 q-rows x one (b,h,w) window, 256 threads (8 warps = 2M x 4N).
// S: [64][516] fp32 logits (stride 2064B); after softmax rewritten in place as
// blocked bf16: per 32B block = 8 hi bf16 then 8 lo bf16 (cols 8b..8b+7).
// 26 pipelined chunk loads: 8 K-chunks, 10 rel-chunks (clamped rows), 8 V-chunks.
#define OFF_QCH 132096
#define OFF_KV  168960
#define OFF_RS  205824
#define ATT_SMEM 206080

__global__ __launch_bounds__(256) void attn_kernel(const float* __restrict__ rcb,
                                                   const float* __restrict__ rpb)
{
    extern __shared__ char smb[];
    float* S = (float*)smb;
    float* rs = (float*)(smb + OFF_RS);
    uint32_t sb = smem_u32(smb);
    int tid = threadIdx.x, wid = tid >> 5, lane = tid & 31;
    int wm = wid & 1, wn = wid >> 1;

    int tt = blockIdx.x & 7, win = blockIdx.x >> 3;
    int bN = win / 96, rem = win - bN * 96, h = rem >> 3, w = rem & 7;
    int t0 = tt << 6;
    size_t base = ((size_t)(bN * 12 + h)) * 4096 + (size_t)w * 512;
    const float* qb = g_q + (base + t0) * 64;
    const __nv_bfloat16 *kh = g_k_hi + base * 64, *klp = g_k_lo + base * 64;
    const __nv_bfloat16 *vh = g_v_hi + base * 64, *vlp = g_v_lo + base * 64;
    const __nv_bfloat16 *rh = g_relk_hi + (size_t)h * 1023 * 64;
    const __nv_bfloat16 *rlp = g_relk_lo + (size_t)h * 1023 * 64;
    int rbase = 448 - t0;

    auto fill = [&](int st, const __nv_bfloat16* ph, const __nv_bfloat16* pl,
                    int row0, int rowmax) {
#pragma unroll
        for (int t = 0; t < 4; t++) {
            int i = tid + t * 256;
            int part = i >> 9, r = (i >> 3) & 63, cc = i & 7;
            int rr = row0 + r; if (rr > rowmax) rr = rowmax;
            const __nv_bfloat16* src = (part ? pl : ph) + (size_t)rr * 64 + cc * 8;
            cp_async16(sb + OFF_KV + st * 18432 + part * 9216 + r * 144 + cc * 16, src);
        }
        cp_commit();
    };

    fill(0, kh, klp, 0, 511);

    // q prep: +bias (fp32), split -> qc hi/lo, qp hi/lo (stride 144B)
    {
        int r = tid >> 2, c0 = (tid & 3) << 4;
#pragma unroll
        for (int i = 0; i < 4; i++) {
            int cc = c0 + i * 4;
            float4 qv = *(const float4*)(qb + r * 64 + cc);
            float4 bc = *(const float4*)(rcb + h * 64 + cc);
            float4 bp = *(const float4*)(rpb + h * 64 + cc);
            uint32_t off = r * 144 + cc * 2;
            uint32_t lo, hi;
            hi = pack_split(qv.x + bc.x, qv.y + bc.y, lo);
            *(uint32_t*)(smb + OFF_QCH + off) = hi;        *(uint32_t*)(smb + OFF_QCH + 9216 + off) = lo;
            hi = pack_split(qv.z + bc.z, qv.w + bc.w, lo);
            *(uint32_t*)(smb + OFF_QCH + off + 4) = hi;    *(uint32_t*)(smb + OFF_QCH + 9216 + off + 4) = lo;
            hi = pack_split(qv.x + bp.x, qv.y + bp.y, lo);
            *(uint32_t*)(smb + OFF_QCH + 18432 + off) = hi;   *(uint32_t*)(smb + OFF_QCH + 27648 + off) = lo;
            hi = pack_split(qv.z + bp.z, qv.w + bp.w, lo);
            *(uint32_t*)(smb + OFF_QCH + 18432 + off + 4) = hi; *(uint32_t*)(smb + OFF_QCH + 27648 + off + 4) = lo;
        }
    }

    float o[2][2][4];
#pragma unroll
    for (int a = 0; a < 2; a++)
#pragma unroll
        for (int bq = 0; bq < 2; bq++)
#pragma unroll
            for (int q = 0; q < 4; q++) o[a][bq][q] = 0.f;

    for (int c = 0; c < 26; c++) {
        if (c < 25) {
            int nc = c + 1;
            if (nc < 8)       fill(nc & 1, kh, klp, nc * 64, 511);
            else if (nc < 18) fill(nc & 1, rh, rlp, rbase + (nc - 8) * 64, 1022);
            else              fill(nc & 1, vh, vlp, (nc - 18) * 64, 511);
            cp_wait1();
        } else cp_wait0();
        __syncthreads();

        if (c == 18) {
            // softmax + in-place P bf16 hi/lo conversion (blocked 32B layout)
            int r = tid >> 2, l4 = tid & 3;
            float* Sr = S + r * 516;
            float mx = -3.0e38f;
            for (int bq = l4; bq < 64; bq += 4) {
                float4 v0 = *(float4*)&Sr[bq * 8];
                float4 v1 = *(float4*)&Sr[bq * 8 + 4];
                mx = fmaxf(mx, fmaxf(fmaxf(v0.x, v0.y), fmaxf(v0.z, v0.w)));
                mx = fmaxf(mx, fmaxf(fmaxf(v1.x, v1.y), fmaxf(v1.z, v1.w)));
            }
            mx = fmaxf(mx, __shfl_xor_sync(0xffffffffu, mx, 1));
            mx = fmaxf(mx, __shfl_xor_sync(0xffffffffu, mx, 2));
            float sum = 0.f;
            for (int bq = l4; bq < 64; bq += 4) {
                float4 v0 = *(float4*)&Sr[bq * 8];
                float4 v1 = *(float4*)&Sr[bq * 8 + 4];
                float e0 = __expf(v0.x - mx), e1 = __expf(v0.y - mx);
                float e2 = __expf(v0.z - mx), e3 = __expf(v0.w - mx);
                float e4 = __expf(v1.x - mx), e5 = __expf(v1.y - mx);
                float e6 = __expf(v1.z - mx), e7 = __expf(v1.w - mx);
                sum += (e0 + e1 + e2 + e3) + (e4 + e5 + e6 + e7);
                uint32_t l0, l1, l2, l3;
                uint32_t h0 = pack_split(e0, e1, l0);
                uint32_t h1 = pack_split(e2, e3, l1);
                uint32_t h2 = pack_split(e4, e5, l2);
                uint32_t h3 = pack_split(e6, e7, l3);
                uint4 hv; hv.x = h0; hv.y = h1; hv.z = h2; hv.w = h3;
                uint4 lv; lv.x = l0; lv.y = l1; lv.z = l2; lv.w = l3;
                *(uint4*)((char*)Sr + bq * 32) = hv;
                *(uint4*)((char*)Sr + bq * 32 + 16) = lv;
            }
            sum += __shfl_xor_sync(0xffffffffu, sum, 1);
            sum += __shfl_xor_sync(0xffffffffu, sum, 2);
            if (l4 == 0) rs[r] = sum;
            __syncthreads();
        }

        uint32_t kvh = sb + OFF_KV + (c & 1) * 18432;
        uint32_t kvl = kvh + 9216;

        if (c < 18) {
            bool isRel = c >= 8;
            uint32_t qh = sb + OFF_QCH + (isRel ? 18432 : 0);
            uint32_t ql = qh + 9216;
            float acc[2][2][4];
#pragma unroll
            for (int a = 0; a < 2; a++)
#pragma unroll
                for (int bq = 0; bq < 2; bq++)
#pragma unroll
                    for (int q = 0; q < 4; q++) acc[a][bq][q] = 0.f;
#pragma unroll
            for (int ks = 0; ks < 4; ks++) {
                uint32_t aoff = (32 * wm + (lane & 15)) * 144 + ks * 32 + ((lane >> 4) << 4);
                uint32_t Ah0[4], Ah1[4], Al0[4], Al1[4], Bh[4], Bl[4];
                ldsm4(Ah0, qh + aoff); ldsm4(Ah1, qh + aoff + 2304);
                ldsm4(Al0, ql + aoff); ldsm4(Al1, ql + aoff + 2304);
                uint32_t boff = (16 * wn + ((lane >> 4) << 3) + (lane & 7)) * 144
                              + ks * 32 + ((lane & 8) << 1);
                ldsm4(Bh, kvh + boff); ldsm4(Bl, kvl + boff);
                mma16816(acc[0][0], Ah0, Bh[0], Bh[1]); mma16816(acc[0][1], Ah0, Bh[2], Bh[3]);
                mma16816(acc[1][0], Ah1, Bh[0], Bh[1]); mma16816(acc[1][1], Ah1, Bh[2], Bh[3]);
                mma16816(acc[0][0], Ah0, Bl[0], Bl[1]); mma16816(acc[0][1], Ah0, Bl[2], Bl[3]);
                mma16816(acc[1][0], Ah1, Bl[0], Bl[1]); mma16816(acc[1][1], Ah1, Bl[2], Bl[3]);
                mma16816(acc[0][0], Al0, Bh[0], Bh[1]); mma16816(acc[0][1], Al0, Bh[2], Bh[3]);
                mma16816(acc[1][0], Al1, Bh[0], Bh[1]); mma16816(acc[1][1], Al1, Bh[2], Bh[3]);
            }
            if (!isRel) {
                int scol = c * 64 + 16 * wn;
#pragma unroll
                for (int mt = 0; mt < 2; mt++) {
                    int t1 = 32 * wm + 16 * mt + (lane >> 2);
#pragma unroll
                    for (int nt = 0; nt < 2; nt++) {
                        int col = scol + 8 * nt + ((lane & 3) << 1);
                        S[t1 * 516 + col]           = acc[mt][nt][0] * 0.125f;
                        S[t1 * 516 + col + 1]       = acc[mt][nt][1] * 0.125f;
                        S[(t1 + 8) * 516 + col]     = acc[mt][nt][2] * 0.125f;
                        S[(t1 + 8) * 516 + col + 1] = acc[mt][nt][3] * 0.125f;
                    }
                }
            } else {
                int colb = (c - 8) * 64 + 16 * wn;
#pragma unroll
                for (int mt = 0; mt < 2; mt++) {
                    int t1 = 32 * wm + 16 * mt + (lane >> 2);
#pragma unroll
                    for (int nt = 0; nt < 2; nt++) {
                        int rl0 = colb + 8 * nt + ((lane & 3) << 1);
                        int s1 = rl0 + t1 - 63;
                        if (s1 >= 0 && s1 < 512)         S[t1 * 516 + s1]           += acc[mt][nt][0];
                        if (s1 + 1 >= 0 && s1 + 1 < 512) S[t1 * 516 + s1 + 1]       += acc[mt][nt][1];
                        int s2 = s1 + 8;
                        if (s2 >= 0 && s2 < 512)         S[(t1 + 8) * 516 + s2]     += acc[mt][nt][2];
                        if (s2 + 1 >= 0 && s2 + 1 < 512) S[(t1 + 8) * 516 + s2 + 1] += acc[mt][nt][3];
                    }
                }
            }
        } else {
            int cv = c - 18;
#pragma unroll
            for (int ks = 0; ks < 4; ks++) {
                uint32_t aoff = (32 * wm + (lane & 15)) * 2064 + cv * 256 + ks * 64
                              + ((lane >> 4) << 5);
                uint32_t Ph0[4], Ph1[4], Pl0[4], Pl1[4], Vh[4], Vl[4];
                ldsm4(Ph0, sb + aoff); ldsm4(Ph1, sb + aoff + 33024);
                ldsm4(Pl0, sb + aoff + 16); ldsm4(Pl1, sb + aoff + 33024 + 16);
                int g = lane >> 3;
                uint32_t boff = (ks * 16 + ((g & 1) << 3) + (lane & 7)) * 144
                              + 32 * wn + ((g >> 1) << 4);
                ldsm4t(Vh, kvh + boff); ldsm4t(Vl, kvl + boff);
                mma16816(o[0][0], Ph0, Vh[0], Vh[1]); mma16816(o[0][1], Ph0, Vh[2], Vh[3]);
                mma16816(o[1][0], Ph1, Vh[0], Vh[1]); mma16816(o[1][1], Ph1, Vh[2], Vh[3]);
                mma16816(o[0][0], Ph0, Vl[0], Vl[1]); mma16816(o[0][1], Ph0, Vl[2], Vl[3]);
                mma16816(o[1][0], Ph1, Vl[0], Vl[1]); mma16816(o[1][1], Ph1, Vl[2], Vl[3]);
                mma16816(o[0][0], Pl0, Vh[0], Vh[1]); mma16816(o[0][1], Pl0, Vh[2], Vh[3]);
                mma16816(o[1][0], Pl1, Vh[0], Vh[1]); mma16816(o[1][1], Pl1, Vh[2], Vh[3]);
            }
        }
        __syncthreads();
    }

    // normalize + write bf16 hi/lo for out-proj
    int colc = 16 * wn;
#pragma unroll
    for (int mt = 0; mt < 2; mt++) {
        int t1 = 32 * wm + 16 * mt + (lane >> 2);
        float i1 = 1.f / rs[t1], i2 = 1.f / rs[t1 + 8];
        size_t row1 = (size_t)bN * 4096 + (size_t)w * 512 + t0 + t1;
#pragma unroll
        for (int nt = 0; nt < 2; nt++) {
            int col = colc + 8 * nt + ((lane & 3) << 1);
            size_t off1 = row1 * 768 + h * 64 + col;
            size_t off2 = (row1 + 8) * 768 + h * 64 + col;
            uint32_t lo, hi;
            hi = pack_split(o[mt][nt][0] * i1, o[mt][nt][1] * i1, lo);
            *(uint32_t*)(g_att_hi + off1) = hi;
            *(uint32_t*)(g_att_lo + off1) = lo;
            hi = pack_split(o[mt][nt][2] * i2, o[mt][nt][3] * i2, lo);
            *(uint32_t*)(g_att_hi + off2) = hi;
            *(uint32_t*)(g_att_lo + off2) = lo;
        }
    }
}

// ================= launch =================
extern "C" void kernel_launch(void* const* d_in, const int* in_sizes, int n_in,
                              void* d_out, int out_size)
{
    const float* x     = (const float*)d_in[0];
    const float* w_qkv = (const float*)d_in[1];
    const float* w_out = (const float*)d_in[2];
    const float* b_out = (const float*)d_in[3];
    const float* w_rel = (const float*)d_in[4];
    const float* rcb   = (const float*)d_in[5];
    const float* rpb   = (const float*)d_in[6];
    float* out = (float*)d_out;

    cudaFuncSetAttribute(attn_kernel, cudaFuncAttributeMaxDynamicSharedMemorySize, ATT_SMEM);
    cudaFuncSetAttribute(mma_gemm, cudaFuncAttributeMaxDynamicSharedMemorySize, GEMM_SMEM);

    __nv_bfloat16 *xh, *xl, *qkvh, *qkvl, *outh, *outl, *relh, *rell, *posh, *posl, *atth, *attl;
    cudaGetSymbolAddress((void**)&xh, g_x_hi);      cudaGetSymbolAddress((void**)&xl, g_x_lo);
    cudaGetSymbolAddress((void**)&qkvh, g_wqkv_hi); cudaGetSymbolAddress((void**)&qkvl, g_wqkv_lo);
    cudaGetSymbolAddress((void**)&outh, g_wout_hi); cudaGetSymbolAddress((void**)&outl, g_wout_lo);
    cudaGetSymbolAddress((void**)&relh, g_wrel_hi); cudaGetSymbolAddress((void**)&rell, g_wrel_lo);
    cudaGetSymbolAddress((void**)&posh, g_pos_hi);  cudaGetSymbolAddress((void**)&posl, g_pos_lo);
    cudaGetSymbolAddress((void**)&atth, g_att_hi);  cudaGetSymbolAddress((void**)&attl, g_att_lo);

    pos_embed_kernel<<<1023, 128>>>();
    split_kernel<<<(6291456 + 255) / 256, 256>>>(x, xh, xl, 6291456);
    splitT_kernel<<<dim3(72, 24), dim3(32, 8)>>>(w_qkv, qkvh, qkvl, 768, 2304);
    splitT_kernel<<<dim3(24, 24), dim3(32, 8)>>>(w_out, outh, outl, 768, 768);
    splitT_kernel<<<dim3(24, 24), dim3(32, 8)>>>(w_rel, relh, rell, 768, 768);

    mma_gemm<<<dim3(24, 64), 256, GEMM_SMEM>>>(xh, xl, qkvh, qkvl, nullptr, nullptr, 0);
    mma_gemm<<<dim3(8, 8), 256, GEMM_SMEM>>>(posh, posl, relh, rell, nullptr, nullptr, 1);
    attn_kernel<<<1536, 256, ATT_SMEM>>>(rcb, rpb);
    mma_gemm<<<dim3(8, 64), 256, GEMM_SMEM>>>(atth, attl, outh, outl, b_out, out, 2);
}

// round 6
// speedup vs baseline: 2.5564x; 1.0004x over previous
#include <cuda_runtime.h>
#include <cuda_bf16.h>
#include <math.h>
#include <stdint.h>

// ================= scratch (device globals) =================
__device__ float g_q[6291456];                         // [B*H][4096][64] fp32
__device__ __nv_bfloat16 g_k_hi[6291456], g_k_lo[6291456];
__device__ __nv_bfloat16 g_v_hi[6291456], g_v_lo[6291456];
__device__ __nv_bfloat16 g_relk_hi[12 * 1023 * 64], g_relk_lo[12 * 1023 * 64];

__device__ __nv_bfloat16 g_x_hi[8192 * 768],   g_x_lo[8192 * 768];
__device__ __nv_bfloat16 g_wqkv_hi[2304 * 768], g_wqkv_lo[2304 * 768];  // [N][K]
__device__ __nv_bfloat16 g_wout_hi[768 * 768],  g_wout_lo[768 * 768];
__device__ __nv_bfloat16 g_wrel_hi[768 * 768],  g_wrel_lo[768 * 768];
__device__ __nv_bfloat16 g_pos_hi[1024 * 768],  g_pos_lo[1024 * 768];
__device__ __nv_bfloat16 g_att_hi[8192 * 768],  g_att_lo[8192 * 768];

// ================= helpers =================
__device__ __forceinline__ uint32_t smem_u32(const void* p) {
    uint32_t a;
    asm("{ .reg .u64 t; cvta.to.shared.u64 t, %1; cvt.u32.u64 %0, t; }" : "=r"(a) : "l"(p));
    return a;
}
__device__ __forceinline__ void cp_async16(uint32_t dst, const void* src) {
    asm volatile("cp.async.ca.shared.global [%0], [%1], 16;" :: "r"(dst), "l"(src));
}
__device__ __forceinline__ void cp_commit() { asm volatile("cp.async.commit_group;"); }
__device__ __forceinline__ void cp_wait1() { asm volatile("cp.async.wait_group 1;"); }
__device__ __forceinline__ void cp_wait0() { asm volatile("cp.async.wait_group 0;"); }

__device__ __forceinline__ void ldsm4(uint32_t* r, uint32_t addr) {
    asm volatile("ldmatrix.sync.aligned.m8n8.x4.shared.b16 {%0,%1,%2,%3}, [%4];"
                 : "=r"(r[0]), "=r"(r[1]), "=r"(r[2]), "=r"(r[3]) : "r"(addr));
}
__device__ __forceinline__ void ldsm4t(uint32_t* r, uint32_t addr) {
    asm volatile("ldmatrix.sync.aligned.m8n8.x4.trans.shared.b16 {%0,%1,%2,%3}, [%4];"
                 : "=r"(r[0]), "=r"(r[1]), "=r"(r[2]), "=r"(r[3]) : "r"(addr));
}
__device__ __forceinline__ void mma16816(float* d, const uint32_t* a, uint32_t b0, uint32_t b1) {
    asm volatile("mma.sync.aligned.m16n8k16.row.col.f32.bf16.bf16.f32 "
                 "{%0,%1,%2,%3}, {%4,%5,%6,%7}, {%8,%9}, {%0,%1,%2,%3};"
                 : "+f"(d[0]), "+f"(d[1]), "+f"(d[2]), "+f"(d[3])
                 : "r"(a[0]), "r"(a[1]), "r"(a[2]), "r"(a[3]), "r"(b0), "r"(b1));
}
__device__ __forceinline__ void split2(float v, __nv_bfloat16& h, __nv_bfloat16& l) {
    h = __float2bfloat16(v);
    l = __float2bfloat16(v - __bfloat162float(h));
}
__device__ __forceinline__ uint32_t pack_split(float a, float b, uint32_t& lo) {
    uint32_t h;
    asm("cvt.rn.bf16x2.f32 %0, %1, %2;" : "=r"(h) : "f"(b), "f"(a));
    float ra = __uint_as_float(h << 16);
    float rb = __uint_as_float(h & 0xffff0000u);
    asm("cvt.rn.bf16x2.f32 %0, %1, %2;" : "=r"(lo) : "f"(b - rb), "f"(a - ra));
    return h;
}

// ================= kernel 1: positional embedding -> bf16 hi/lo =================
__global__ void pos_embed_kernel() {
    int r = blockIdx.x;          // dist = r - 511
    int j = threadIdx.x;
    float dist = (float)(r - 511);
    double p = fabs((double)dist);

    double hl = exp2(3.0 + (double)j * (6.0 / 127.0));
    float ef = (float)exp(-0.6931471805599453 / hl * p);

    float cw = exp2f((float)(j + 1)) - 1.0f;
    float cm = (cw > (float)p) ? 1.0f : 0.0f;

    double mean = 4.0 * (double)(j + 1);
    double conc = (mean * 0.5) * (mean * 0.5);
    double rate = mean * 0.25;
    double lp = -rate * p - (lgamma(conc) - conc * log(rate));
    if (p > 0.0) lp += (conc - 1.0) * log(p);
    double prob = ((p > 0.0) ? exp(lp) : 0.0) + 1e-8;  // xlogy(c-1,0) = -inf -> 0

    __shared__ double red[128];
    red[j] = prob;
    __syncthreads();
    for (int o = 64; o > 0; o >>= 1) {
        if (j < o) red[j] = fmax(red[j], red[j + o]);
        __syncthreads();
    }
    float gf = (float)(prob / red[0]);

    float sg = (dist > 0.f) ? 1.f : ((dist < 0.f) ? -1.f : 0.f);
    float vals[6] = {ef, cm, gf, sg * ef, sg * cm, sg * gf};
    size_t base = (size_t)r * 768;
#pragma unroll
    for (int s = 0; s < 6; s++) {
        __nv_bfloat16 h, l;
        split2(vals[s], h, l);
        g_pos_hi[base + s * 128 + j] = h;
        g_pos_lo[base + s * 128 + j] = l;
    }
}

// ================= split kernels =================
__global__ void split_kernel(const float* __restrict__ s, __nv_bfloat16* __restrict__ h,
                             __nv_bfloat16* __restrict__ l, int n) {
    int i = blockIdx.x * 256 + threadIdx.x;
    if (i < n) split2(s[i], h[i], l[i]);
}

__global__ void splitT_kernel(const float* __restrict__ src, __nv_bfloat16* __restrict__ hi,
                              __nv_bfloat16* __restrict__ lo, int K, int N) {
    __shared__ float t[32][33];
    int n0 = blockIdx.x * 32, k0 = blockIdx.y * 32;
    int x = threadIdx.x, y0 = threadIdx.y;
#pragma unroll
    for (int i = 0; i < 4; i++) {
        int y = y0 + i * 8;
        t[y][x] = src[(size_t)(k0 + y) * N + n0 + x];
    }
    __syncthreads();
#pragma unroll
    for (int i = 0; i < 4; i++) {
        int y = y0 + i * 8;
        float v = t[x][y];
        __nv_bfloat16 a, b;
        split2(v, a, b);
        size_t o = (size_t)(n0 + y) * K + k0 + x;
        hi[o] = a; lo[o] = b;
    }
}

// ================= kernel 2: mma.sync bf16x2-split GEMM (2 CTAs/SM) =================
#define APB 10240
#define BPB 7680
#define STG 35840
#define GEMM_SMEM (2 * STG)
#define S_ST 100

__global__ __launch_bounds__(256, 2) void mma_gemm(
    const __nv_bfloat16* __restrict__ Ah, const __nv_bfloat16* __restrict__ Al,
    const __nv_bfloat16* __restrict__ Bh, const __nv_bfloat16* __restrict__ Bl,
    const float* __restrict__ bias, float* __restrict__ Cout, int mode)
{
    extern __shared__ char dsm[];
    uint32_t sbase = smem_u32(dsm);
    int tid = threadIdx.x, wid = tid >> 5, lane = tid & 31;
    int wm = wid & 3, wn = wid >> 2;

    size_t m0 = (size_t)blockIdx.y * 128;
    int n0 = blockIdx.x * 96;

    float acc[2][6][4];
#pragma unroll
    for (int i = 0; i < 2; i++)
#pragma unroll
        for (int j = 0; j < 6; j++)
#pragma unroll
            for (int q = 0; q < 4; q++) acc[i][j][q] = 0.f;

    int a_lr = lane & 15;
    int a_lc = (lane >> 4) << 3;
    int b_ln = ((lane >> 4) << 3) + (lane & 7);
    int b_lk = lane & 8;

    auto fill = [&](int s, int c) {
        uint32_t st = sbase + s * STG;
        int k0 = c * 32;
#pragma unroll
        for (int ii = 0; ii < 7; ii++) {
            int i = tid + ii * 256;
            if (i < 1024) {
                int part = i >> 9, rr = (i >> 2) & 127, cc = i & 3;
                const __nv_bfloat16* src = (part ? Al : Ah) + (m0 + rr) * 768 + k0 + cc * 8;
                cp_async16(st + part * APB + rr * 80 + cc * 16, src);
            } else {
                int j = i - 1024;
                int part = j >= 384; int jj = j - (part ? 384 : 0);
                int rr = jj >> 2, cc = jj & 3;
                const __nv_bfloat16* src = (part ? Bl : Bh) + (size_t)(n0 + rr) * 768 + k0 + cc * 8;
                cp_async16(st + 2 * APB + part * BPB + rr * 80 + cc * 16, src);
            }
        }
        cp_commit();
    };

    fill(0, 0);
    for (int c = 0; c < 24; c++) {
        if (c < 23) { fill((c + 1) & 1, c + 1); cp_wait1(); } else { cp_wait0(); }
        __syncthreads();

        uint32_t st = sbase + (c & 1) * STG;
#pragma unroll
        for (int step = 0; step < 2; step++) {
            uint32_t ab = st + (wm * 32 + a_lr) * 80 + (step * 16 + a_lc) * 2;
            uint32_t bb = st + 2 * APB + (wn * 48 + b_ln) * 80 + (step * 16 + b_lk) * 2;
            uint32_t Af[2][4], Alf[2][4], Bf[3][4], Blf[3][4];
            ldsm4(Af[0], ab);           ldsm4(Af[1], ab + 1280);
            ldsm4(Alf[0], ab + APB);    ldsm4(Alf[1], ab + APB + 1280);
#pragma unroll
            for (int ng = 0; ng < 3; ng++) {
                ldsm4(Bf[ng],  bb + ng * 1280);
                ldsm4(Blf[ng], bb + BPB + ng * 1280);
            }
#pragma unroll
            for (int mi = 0; mi < 2; mi++)
#pragma unroll
                for (int ng = 0; ng < 3; ng++) {
                    mma16816(acc[mi][ng * 2 + 0], Af[mi],  Bf[ng][0],  Bf[ng][1]);
                    mma16816(acc[mi][ng * 2 + 0], Af[mi],  Blf[ng][0], Blf[ng][1]);
                    mma16816(acc[mi][ng * 2 + 0], Alf[mi], Bf[ng][0],  Bf[ng][1]);
                    mma16816(acc[mi][ng * 2 + 1], Af[mi],  Bf[ng][2],  Bf[ng][3]);
                    mma16816(acc[mi][ng * 2 + 1], Af[mi],  Blf[ng][2], Blf[ng][3]);
                    mma16816(acc[mi][ng * 2 + 1], Alf[mi], Bf[ng][2],  Bf[ng][3]);
                }
        }
        __syncthreads();
    }

    float* S = (float*)dsm;
#pragma unroll
    for (int mi = 0; mi < 2; mi++)
#pragma unroll
        for (int nj = 0; nj < 6; nj++) {
            int row = wm * 32 + mi * 16 + (lane >> 2);
            int col = wn * 48 + nj * 8 + (lane & 3) * 2;
            S[row * S_ST + col]             = acc[mi][nj][0];
            S[row * S_ST + col + 1]         = acc[mi][nj][1];
            S[(row + 8) * S_ST + col]       = acc[mi][nj][2];
            S[(row + 8) * S_ST + col + 1]   = acc[mi][nj][3];
        }
    __syncthreads();

    if (mode == 0) {
        int hh = blockIdx.x >> 1;
        int dbase = (blockIdx.x & 1) * 32;
        int bi = (int)(m0 >> 12);
        int nn0 = (int)(m0 & 4095);
        size_t ob = ((size_t)(bi * 12 + hh) * 4096 + nn0) * 64 + dbase;
        for (int task = wid; task < 384; task += 8) {
            int mm = task / 3;
            int which = task - 3 * mm;
            float v = S[mm * S_ST + 3 * lane + which];
            size_t o = ob + (size_t)mm * 64 + lane;
            if (which == 0) g_q[o] = v;
            else {
                __nv_bfloat16 hv, lv; split2(v, hv, lv);
                if (which == 1) { g_k_hi[o] = hv; g_k_lo[o] = lv; }
                else            { g_v_hi[o] = hv; g_v_lo[o] = lv; }
            }
        }
    } else if (mode == 1) {
        for (int task = wid; task < 384; task += 8) {
            int mm = task / 3;
            int g = task - 3 * mm;
            int cgl = n0 + g * 32 + lane;
            int hh = cgl >> 6, d = cgl & 63;
            int r = (int)m0 + mm;
            if (r < 1023) {
                __nv_bfloat16 hv, lv; split2(S[mm * S_ST + g * 32 + lane], hv, lv);
                size_t o = ((size_t)hh * 1023 + r) * 64 + d;
                g_relk_hi[o] = hv; g_relk_lo[o] = lv;
            }
        }
    } else {
        for (int task = wid; task < 384; task += 8) {
            int mm = task / 3;
            int g = task - 3 * mm;
            int j = g * 32 + lane;
            Cout[(m0 + mm) * 768 + n0 + j] = S[mm * S_ST + j] + bias[n0 + j];
        }
    }
}

// ================= kernel 3: tensor-core fused window attention =================
// 25 chunks: 8 K (content), 9 rel (rl 0..575 covers all valid s), 8 V.
// 3-stage KV ring, ONE sync per chunk: wait(buf c) -> sync -> fill(c+2) -> compute(c).
#define OFF_QCH 132096
#define OFF_KV  168960
#define OFF_RS  224256
#define ATT_SMEM 224512

__global__ __launch_bounds__(256) void attn_kernel(const float* __restrict__ rcb,
                                                   const float* __restrict__ rpb)
{
    extern __shared__ char smb[];
    float* S = (float*)smb;
    float* rs = (float*)(smb + OFF_RS);
    uint32_t sb = smem_u32(smb);
    int tid = threadIdx.x, wid = tid >> 5, lane = tid & 31;
    int wm = wid & 1, wn = wid >> 1;

    int tt = blockIdx.x & 7, win = blockIdx.x >> 3;
    int bN = win / 96, rem = win - bN * 96, h = rem >> 3, w = rem & 7;
    int t0 = tt << 6;
    size_t base = ((size_t)(bN * 12 + h)) * 4096 + (size_t)w * 512;
    const float* qb = g_q + (base + t0) * 64;
    const __nv_bfloat16 *kh = g_k_hi + base * 64, *klp = g_k_lo + base * 64;
    const __nv_bfloat16 *vh = g_v_hi + base * 64, *vlp = g_v_lo + base * 64;
    const __nv_bfloat16 *rh = g_relk_hi + (size_t)h * 1023 * 64;
    const __nv_bfloat16 *rlp = g_relk_lo + (size_t)h * 1023 * 64;
    int rbase = 448 - t0;

    auto fillChunk = [&](int ch) {
        int st = ch % 3;
        const __nv_bfloat16 *ph, *pl;
        int row0, rowmax;
        if (ch < 8)       { ph = kh; pl = klp; row0 = ch * 64; rowmax = 511; }
        else if (ch < 17) { ph = rh; pl = rlp; row0 = rbase + (ch - 8) * 64; rowmax = 1022; }
        else              { ph = vh; pl = vlp; row0 = (ch - 17) * 64; rowmax = 511; }
#pragma unroll
        for (int t = 0; t < 4; t++) {
            int i = tid + t * 256;
            int part = i >> 9, r = (i >> 3) & 63, cc = i & 7;
            int rr = row0 + r; if (rr > rowmax) rr = rowmax;
            const __nv_bfloat16* src = (part ? pl : ph) + (size_t)rr * 64 + cc * 8;
            cp_async16(sb + OFF_KV + st * 18432 + part * 9216 + r * 144 + cc * 16, src);
        }
        cp_commit();
    };

    fillChunk(0);
    fillChunk(1);

    // q prep: +bias (fp32), split -> qc hi/lo, qp hi/lo (stride 144B)
    {
        int r = tid >> 2, c0 = (tid & 3) << 4;
#pragma unroll
        for (int i = 0; i < 4; i++) {
            int cc = c0 + i * 4;
            float4 qv = *(const float4*)(qb + r * 64 + cc);
            float4 bc = *(const float4*)(rcb + h * 64 + cc);
            float4 bp = *(const float4*)(rpb + h * 64 + cc);
            uint32_t off = r * 144 + cc * 2;
            uint32_t lo, hi;
            hi = pack_split(qv.x + bc.x, qv.y + bc.y, lo);
            *(uint32_t*)(smb + OFF_QCH + off) = hi;        *(uint32_t*)(smb + OFF_QCH + 9216 + off) = lo;
            hi = pack_split(qv.z + bc.z, qv.w + bc.w, lo);
            *(uint32_t*)(smb + OFF_QCH + off + 4) = hi;    *(uint32_t*)(smb + OFF_QCH + 9216 + off + 4) = lo;
            hi = pack_split(qv.x + bp.x, qv.y + bp.y, lo);
            *(uint32_t*)(smb + OFF_QCH + 18432 + off) = hi;   *(uint32_t*)(smb + OFF_QCH + 27648 + off) = lo;
            hi = pack_split(qv.z + bp.z, qv.w + bp.w, lo);
            *(uint32_t*)(smb + OFF_QCH + 18432 + off + 4) = hi; *(uint32_t*)(smb + OFF_QCH + 27648 + off + 4) = lo;
        }
    }

    float o[2][2][4];
#pragma unroll
    for (int a = 0; a < 2; a++)
#pragma unroll
        for (int bq = 0; bq < 2; bq++)
#pragma unroll
            for (int q = 0; q < 4; q++) o[a][bq][q] = 0.f;

    for (int c = 0; c < 25; c++) {
        if (c < 24) cp_wait1(); else cp_wait0();
        __syncthreads();

        if (c == 17) {
            // softmax + in-place P bf16 hi/lo conversion (blocked 32B layout)
            int r = tid >> 2, l4 = tid & 3;
            float* Sr = S + r * 516;
            float mx = -3.0e38f;
            for (int bq = l4; bq < 64; bq += 4) {
                float4 v0 = *(float4*)&Sr[bq * 8];
                float4 v1 = *(float4*)&Sr[bq * 8 + 4];
                mx = fmaxf(mx, fmaxf(fmaxf(v0.x, v0.y), fmaxf(v0.z, v0.w)));
                mx = fmaxf(mx, fmaxf(fmaxf(v1.x, v1.y), fmaxf(v1.z, v1.w)));
            }
            mx = fmaxf(mx, __shfl_xor_sync(0xffffffffu, mx, 1));
            mx = fmaxf(mx, __shfl_xor_sync(0xffffffffu, mx, 2));
            float sum = 0.f;
            for (int bq = l4; bq < 64; bq += 4) {
                float4 v0 = *(float4*)&Sr[bq * 8];
                float4 v1 = *(float4*)&Sr[bq * 8 + 4];
                float e0 = __expf(v0.x - mx), e1 = __expf(v0.y - mx);
                float e2 = __expf(v0.z - mx), e3 = __expf(v0.w - mx);
                float e4 = __expf(v1.x - mx), e5 = __expf(v1.y - mx);
                float e6 = __expf(v1.z - mx), e7 = __expf(v1.w - mx);
                sum += (e0 + e1 + e2 + e3) + (e4 + e5 + e6 + e7);
                uint32_t l0, l1, l2, l3;
                uint32_t h0 = pack_split(e0, e1, l0);
                uint32_t h1 = pack_split(e2, e3, l1);
                uint32_t h2 = pack_split(e4, e5, l2);
                uint32_t h3 = pack_split(e6, e7, l3);
                uint4 hv; hv.x = h0; hv.y = h1; hv.z = h2; hv.w = h3;
                uint4 lv; lv.x = l0; lv.y = l1; lv.z = l2; lv.w = l3;
                *(uint4*)((char*)Sr + bq * 32) = hv;
                *(uint4*)((char*)Sr + bq * 32 + 16) = lv;
            }
            sum += __shfl_xor_sync(0xffffffffu, sum, 1);
            sum += __shfl_xor_sync(0xffffffffu, sum, 2);
            if (l4 == 0) rs[r] = sum;
            __syncthreads();
        }

        if (c <= 22) fillChunk(c + 2);

        uint32_t kvh = sb + OFF_KV + (c % 3) * 18432;
        uint32_t kvl = kvh + 9216;

        if (c < 17) {
            bool isRel = c >= 8;
            uint32_t qh = sb + OFF_QCH + (isRel ? 18432 : 0);
            uint32_t ql = qh + 9216;
            float acc[2][2][4];
#pragma unroll
            for (int a = 0; a < 2; a++)
#pragma unroll
                for (int bq = 0; bq < 2; bq++)
#pragma unroll
                    for (int q = 0; q < 4; q++) acc[a][bq][q] = 0.f;
#pragma unroll
            for (int ks = 0; ks < 4; ks++) {
                uint32_t aoff = (32 * wm + (lane & 15)) * 144 + ks * 32 + ((lane >> 4) << 4);
                uint32_t Ah0[4], Ah1[4], Al0[4], Al1[4], Bh[4], Bl[4];
                ldsm4(Ah0, qh + aoff); ldsm4(Ah1, qh + aoff + 2304);
                ldsm4(Al0, ql + aoff); ldsm4(Al1, ql + aoff + 2304);
                uint32_t boff = (16 * wn + ((lane >> 4) << 3) + (lane & 7)) * 144
                              + ks * 32 + ((lane & 8) << 1);
                ldsm4(Bh, kvh + boff); ldsm4(Bl, kvl + boff);
                mma16816(acc[0][0], Ah0, Bh[0], Bh[1]); mma16816(acc[0][1], Ah0, Bh[2], Bh[3]);
                mma16816(acc[1][0], Ah1, Bh[0], Bh[1]); mma16816(acc[1][1], Ah1, Bh[2], Bh[3]);
                mma16816(acc[0][0], Ah0, Bl[0], Bl[1]); mma16816(acc[0][1], Ah0, Bl[2], Bl[3]);
                mma16816(acc[1][0], Ah1, Bl[0], Bl[1]); mma16816(acc[1][1], Ah1, Bl[2], Bl[3]);
                mma16816(acc[0][0], Al0, Bh[0], Bh[1]); mma16816(acc[0][1], Al0, Bh[2], Bh[3]);
                mma16816(acc[1][0], Al1, Bh[0], Bh[1]); mma16816(acc[1][1], Al1, Bh[2], Bh[3]);
            }
            if (!isRel) {
                int scol = c * 64 + 16 * wn;
#pragma unroll
                for (int mt = 0; mt < 2; mt++) {
                    int t1 = 32 * wm + 16 * mt + (lane >> 2);
#pragma unroll
                    for (int nt = 0; nt < 2; nt++) {
                        int col = scol + 8 * nt + ((lane & 3) << 1);
                        S[t1 * 516 + col]           = acc[mt][nt][0] * 0.125f;
                        S[t1 * 516 + col + 1]       = acc[mt][nt][1] * 0.125f;
                        S[(t1 + 8) * 516 + col]     = acc[mt][nt][2] * 0.125f;
                        S[(t1 + 8) * 516 + col + 1] = acc[mt][nt][3] * 0.125f;
                    }
                }
            } else {
                int colb = (c - 8) * 64 + 16 * wn;
#pragma unroll
                for (int mt = 0; mt < 2; mt++) {
                    int t1 = 32 * wm + 16 * mt + (lane >> 2);
#pragma unroll
                    for (int nt = 0; nt < 2; nt++) {
                        int rl0 = colb + 8 * nt + ((lane & 3) << 1);
                        int s1 = rl0 + t1 - 63;
                        if (s1 >= 0 && s1 < 512)         S[t1 * 516 + s1]           += acc[mt][nt][0];
                        if (s1 + 1 >= 0 && s1 + 1 < 512) S[t1 * 516 + s1 + 1]       += acc[mt][nt][1];
                        int s2 = s1 + 8;
                        if (s2 >= 0 && s2 < 512)         S[(t1 + 8) * 516 + s2]     += acc[mt][nt][2];
                        if (s2 + 1 >= 0 && s2 + 1 < 512) S[(t1 + 8) * 516 + s2 + 1] += acc[mt][nt][3];
                    }
                }
            }
        } else {
            int cv = c - 17;
#pragma unroll
            for (int ks = 0; ks < 4; ks++) {
                uint32_t aoff = (32 * wm + (lane & 15)) * 2064 + cv * 256 + ks * 64
                              + ((lane >> 4) << 5);
                uint32_t Ph0[4], Ph1[4], Pl0[4], Pl1[4], Vh[4], Vl[4];
                ldsm4(Ph0, sb + aoff); ldsm4(Ph1, sb + aoff + 33024);
                ldsm4(Pl0, sb + aoff + 16); ldsm4(Pl1, sb + aoff + 33024 + 16);
                int g = lane >> 3;
                uint32_t boff = (ks * 16 + ((g & 1) << 3) + (lane & 7)) * 144
                              + 32 * wn + ((g >> 1) << 4);
                ldsm4t(Vh, kvh + boff); ldsm4t(Vl, kvl + boff);
                mma16816(o[0][0], Ph0, Vh[0], Vh[1]); mma16816(o[0][1], Ph0, Vh[2], Vh[3]);
                mma16816(o[1][0], Ph1, Vh[0], Vh[1]); mma16816(o[1][1], Ph1, Vh[2], Vh[3]);
                mma16816(o[0][0], Ph0, Vl[0], Vl[1]); mma16816(o[0][1], Ph0, Vl[2], Vl[3]);
                mma16816(o[1][0], Ph1, Vl[0], Vl[1]); mma16816(o[1][1], Ph1, Vl[2], Vl[3]);
                mma16816(o[0][0], Pl0, Vh[0], Vh[1]); mma16816(o[0][1], Pl0, Vh[2], Vh[3]);
                mma16816(o[1][0], Pl1, Vh[0], Vh[1]); mma16816(o[1][1], Pl1, Vh[2], Vh[3]);
            }
        }
    }

    // normalize + write bf16 hi/lo for out-proj
    int colc = 16 * wn;
#pragma unroll
    for (int mt = 0; mt < 2; mt++) {
        int t1 = 32 * wm + 16 * mt + (lane >> 2);
        float i1 = 1.f / rs[t1], i2 = 1.f / rs[t1 + 8];
        size_t row1 = (size_t)bN * 4096 + (size_t)w * 512 + t0 + t1;
#pragma unroll
        for (int nt = 0; nt < 2; nt++) {
            int col = colc + 8 * nt + ((lane & 3) << 1);
            size_t off1 = row1 * 768 + h * 64 + col;
            size_t off2 = (row1 + 8) * 768 + h * 64 + col;
            uint32_t lo, hi;
            hi = pack_split(o[mt][nt][0] * i1, o[mt][nt][1] * i1, lo);
            *(uint32_t*)(g_att_hi + off1) = hi;
            *(uint32_t*)(g_att_lo + off1) = lo;
            hi = pack_split(o[mt][nt][2] * i2, o[mt][nt][3] * i2, lo);
            *(uint32_t*)(g_att_hi + off2) = hi;
            *(uint32_t*)(g_att_lo + off2) = lo;
        }
    }
}

// ================= launch =================
extern "C" void kernel_launch(void* const* d_in, const int* in_sizes, int n_in,
                              void* d_out, int out_size)
{
    const float* x     = (const float*)d_in[0];
    const float* w_qkv = (const float*)d_in[1];
    const float* w_out = (const float*)d_in[2];
    const float* b_out = (const float*)d_in[3];
    const float* w_rel = (const float*)d_in[4];
    const float* rcb   = (const float*)d_in[5];
    const float* rpb   = (const float*)d_in[6];
    float* out = (float*)d_out;

    cudaFuncSetAttribute(attn_kernel, cudaFuncAttributeMaxDynamicSharedMemorySize, ATT_SMEM);
    cudaFuncSetAttribute(mma_gemm, cudaFuncAttributeMaxDynamicSharedMemorySize, GEMM_SMEM);

    __nv_bfloat16 *xh, *xl, *qkvh, *qkvl, *outh, *outl, *relh, *rell, *posh, *posl, *atth, *attl;
    cudaGetSymbolAddress((void**)&xh, g_x_hi);      cudaGetSymbolAddress((void**)&xl, g_x_lo);
    cudaGetSymbolAddress((void**)&qkvh, g_wqkv_hi); cudaGetSymbolAddress((void**)&qkvl, g_wqkv_lo);
    cudaGetSymbolAddress((void**)&outh, g_wout_hi); cudaGetSymbolAddress((void**)&outl, g_wout_lo);
    cudaGetSymbolAddress((void**)&relh, g_wrel_hi); cudaGetSymbolAddress((void**)&rell, g_wrel_lo);
    cudaGetSymbolAddress((void**)&posh, g_pos_hi);  cudaGetSymbolAddress((void**)&posl, g_pos_lo);
    cudaGetSymbolAddress((void**)&atth, g_att_hi);  cudaGetSymbolAddress((void**)&attl, g_att_lo);

    pos_embed_kernel<<<1023, 128>>>();
    split_kernel<<<(6291456 + 255) / 256, 256>>>(x, xh, xl, 6291456);
    splitT_kernel<<<dim3(72, 24), dim3(32, 8)>>>(w_qkv, qkvh, qkvl, 768, 2304);
    splitT_kernel<<<dim3(24, 24), dim3(32, 8)>>>(w_out, outh, outl, 768, 768);
    splitT_kernel<<<dim3(24, 24), dim3(32, 8)>>>(w_rel, relh, rell, 768, 768);

    mma_gemm<<<dim3(24, 64), 256, GEMM_SMEM>>>(xh, xl, qkvh, qkvl, nullptr, nullptr, 0);
    mma_gemm<<<dim3(8, 8), 256, GEMM_SMEM>>>(posh, posl, relh, rell, nullptr, nullptr, 1);
    attn_kernel<<<1536, 256, ATT_SMEM>>>(rcb, rpb);
    mma_gemm<<<dim3(8, 64), 256, GEMM_SMEM>>>(atth, attl, outh, outl, b_out, out, 2);
}

// round 7
// speedup vs baseline: 2.7283x; 1.0672x over previous
#include <cuda_runtime.h>
#include <cuda_bf16.h>
#include <math.h>
#include <stdint.h>

// ================= scratch (device globals) =================
__device__ float g_q[6291456];                         // [B*H][4096][64] fp32
__device__ __nv_bfloat16 g_k_hi[6291456], g_k_lo[6291456];
__device__ __nv_bfloat16 g_v_hi[6291456], g_v_lo[6291456];
__device__ __nv_bfloat16 g_relk_hi[12 * 1023 * 64], g_relk_lo[12 * 1023 * 64];

__device__ __nv_bfloat16 g_x_hi[8192 * 768],   g_x_lo[8192 * 768];
__device__ __nv_bfloat16 g_wqkv_hi[2304 * 768], g_wqkv_lo[2304 * 768];  // [N][K]
__device__ __nv_bfloat16 g_wout_hi[768 * 768],  g_wout_lo[768 * 768];
__device__ __nv_bfloat16 g_wrel_hi[768 * 768],  g_wrel_lo[768 * 768];
__device__ __nv_bfloat16 g_pos_hi[1024 * 768],  g_pos_lo[1024 * 768];   // row 1023 stays zero
__device__ __nv_bfloat16 g_att_hi[8192 * 768],  g_att_lo[8192 * 768];

// ================= helpers =================
__device__ __forceinline__ uint32_t smem_u32(const void* p) {
    uint32_t a;
    asm("{ .reg .u64 t; cvta.to.shared.u64 t, %1; cvt.u32.u64 %0, t; }" : "=r"(a) : "l"(p));
    return a;
}
__device__ __forceinline__ void cp_async16(uint32_t dst, const void* src) {
    asm volatile("cp.async.ca.shared.global [%0], [%1], 16;" :: "r"(dst), "l"(src));
}
__device__ __forceinline__ void cp_commit() { asm volatile("cp.async.commit_group;"); }
__device__ __forceinline__ void cp_wait1() { asm volatile("cp.async.wait_group 1;"); }
__device__ __forceinline__ void cp_wait0() { asm volatile("cp.async.wait_group 0;"); }

__device__ __forceinline__ void ldsm4(uint32_t* r, uint32_t addr) {
    asm volatile("ldmatrix.sync.aligned.m8n8.x4.shared.b16 {%0,%1,%2,%3}, [%4];"
                 : "=r"(r[0]), "=r"(r[1]), "=r"(r[2]), "=r"(r[3]) : "r"(addr));
}
__device__ __forceinline__ void ldsm4t(uint32_t* r, uint32_t addr) {
    asm volatile("ldmatrix.sync.aligned.m8n8.x4.trans.shared.b16 {%0,%1,%2,%3}, [%4];"
                 : "=r"(r[0]), "=r"(r[1]), "=r"(r[2]), "=r"(r[3]) : "r"(addr));
}
__device__ __forceinline__ void mma16816(float* d, const uint32_t* a, uint32_t b0, uint32_t b1) {
    asm volatile("mma.sync.aligned.m16n8k16.row.col.f32.bf16.bf16.f32 "
                 "{%0,%1,%2,%3}, {%4,%5,%6,%7}, {%8,%9}, {%0,%1,%2,%3};"
                 : "+f"(d[0]), "+f"(d[1]), "+f"(d[2]), "+f"(d[3])
                 : "r"(a[0]), "r"(a[1]), "r"(a[2]), "r"(a[3]), "r"(b0), "r"(b1));
}
__device__ __forceinline__ void split2(float v, __nv_bfloat16& h, __nv_bfloat16& l) {
    h = __float2bfloat16(v);
    l = __float2bfloat16(v - __bfloat162float(h));
}
__device__ __forceinline__ uint32_t pack_split(float a, float b, uint32_t& lo) {
    uint32_t h;
    asm("cvt.rn.bf16x2.f32 %0, %1, %2;" : "=r"(h) : "f"(b), "f"(a));
    float ra = __uint_as_float(h << 16);
    float rb = __uint_as_float(h & 0xffff0000u);
    asm("cvt.rn.bf16x2.f32 %0, %1, %2;" : "=r"(lo) : "f"(b - rb), "f"(a - ra));
    return h;
}

// ================= kernel 1: merged prologue =================
// blocks [0,2048): x split (grid-stride, 12 iters)
// [2048,3776): splitT wqkv (72x24); [3776,4352): splitT wout (24x24);
// [4352,4928): splitT wrel (24x24); [4928,5440): pos_embed (2 rows/block)
__device__ __forceinline__ void splitT_body(const float* __restrict__ src,
                                            __nv_bfloat16* __restrict__ hi,
                                            __nv_bfloat16* __restrict__ lo,
                                            int K, int N, int bx, int by, int tid,
                                            float (*t)[33]) {
    int n0 = bx * 32, k0 = by * 32;
    int x = tid & 31, y0 = tid >> 5;
#pragma unroll
    for (int i = 0; i < 4; i++) {
        int y = y0 + i * 8;
        t[y][x] = src[(size_t)(k0 + y) * N + n0 + x];
    }
    __syncthreads();
#pragma unroll
    for (int i = 0; i < 4; i++) {
        int y = y0 + i * 8;
        float v = t[x][y];
        __nv_bfloat16 a, b;
        split2(v, a, b);
        size_t o = (size_t)(n0 + y) * K + k0 + x;
        hi[o] = a; lo[o] = b;
    }
}

__global__ __launch_bounds__(256) void prep_kernel(
    const float* __restrict__ x, const float* __restrict__ w_qkv,
    const float* __restrict__ w_out, const float* __restrict__ w_rel)
{
    __shared__ float t[32][33];
    __shared__ double red[2][128];
    int bid = blockIdx.x, tid = threadIdx.x;

    if (bid < 2048) {
#pragma unroll
        for (int it = 0; it < 12; it++) {
            int i = (bid * 12 + it) * 256 + tid;
            split2(x[i], g_x_hi[i], g_x_lo[i]);
        }
    } else if (bid < 3776) {
        int rid = bid - 2048;
        splitT_body(w_qkv, g_wqkv_hi, g_wqkv_lo, 768, 2304, rid % 72, rid / 72, tid, t);
    } else if (bid < 4352) {
        int rid = bid - 3776;
        splitT_body(w_out, g_wout_hi, g_wout_lo, 768, 768, rid % 24, rid / 24, tid, t);
    } else if (bid < 4928) {
        int rid = bid - 4352;
        splitT_body(w_rel, g_wrel_hi, g_wrel_lo, 768, 768, rid % 24, rid / 24, tid, t);
    } else {
        // pos embed: 2 rows per block
        int half = tid >> 7, j = tid & 127;
        int r = (bid - 4928) * 2 + half;          // 0..1023
        int rr = (r < 1023) ? r : 1022;           // clamp row 1023 (skip store)
        float dist = (float)(rr - 511);
        double p = fabs((double)dist);

        double hl = exp2(3.0 + (double)j * (6.0 / 127.0));
        float ef = (float)exp(-0.6931471805599453 / hl * p);

        float cw = exp2f((float)(j + 1)) - 1.0f;
        float cm = (cw > (float)p) ? 1.0f : 0.0f;

        double mean = 4.0 * (double)(j + 1);
        double conc = (mean * 0.5) * (mean * 0.5);
        double rate = mean * 0.25;
        double lp = -rate * p - (lgamma(conc) - conc * log(rate));
        if (p > 0.0) lp += (conc - 1.0) * log(p);
        double prob = ((p > 0.0) ? exp(lp) : 0.0) + 1e-8;  // xlogy(c-1,0) -> -inf -> 0

        red[half][j] = prob;
        __syncthreads();
        for (int o = 64; o > 0; o >>= 1) {
            if (j < o) red[half][j] = fmax(red[half][j], red[half][j + o]);
            __syncthreads();
        }
        float gf = (float)(prob / red[half][0]);

        float sg = (dist > 0.f) ? 1.f : ((dist < 0.f) ? -1.f : 0.f);
        float vals[6] = {ef, cm, gf, sg * ef, sg * cm, sg * gf};
        if (r < 1023) {
            size_t base = (size_t)r * 768;
#pragma unroll
            for (int s = 0; s < 6; s++) {
                __nv_bfloat16 h, l;
                split2(vals[s], h, l);
                g_pos_hi[base + s * 128 + j] = h;
                g_pos_lo[base + s * 128 + j] = l;
            }
        }
    }
}

// ================= mma.sync bf16x2-split GEMM body =================
#define APB 10240
#define BPB 7680
#define STG 35840
#define GEMM_SMEM (2 * STG)
#define S_ST 100

__device__ __forceinline__ void mma_gemm_body(
    int bx, int by,
    const __nv_bfloat16* __restrict__ Ah, const __nv_bfloat16* __restrict__ Al,
    const __nv_bfloat16* __restrict__ Bh, const __nv_bfloat16* __restrict__ Bl,
    const float* __restrict__ bias, float* __restrict__ Cout, int mode)
{
    extern __shared__ char dsm[];
    uint32_t sbase = smem_u32(dsm);
    int tid = threadIdx.x, wid = tid >> 5, lane = tid & 31;
    int wm = wid & 3, wn = wid >> 2;

    size_t m0 = (size_t)by * 128;
    int n0 = bx * 96;

    float acc[2][6][4];
#pragma unroll
    for (int i = 0; i < 2; i++)
#pragma unroll
        for (int j = 0; j < 6; j++)
#pragma unroll
            for (int q = 0; q < 4; q++) acc[i][j][q] = 0.f;

    int a_lr = lane & 15;
    int a_lc = (lane >> 4) << 3;
    int b_ln = ((lane >> 4) << 3) + (lane & 7);
    int b_lk = lane & 8;

    auto fill = [&](int s, int c) {
        uint32_t st = sbase + s * STG;
        int k0 = c * 32;
#pragma unroll
        for (int ii = 0; ii < 7; ii++) {
            int i = tid + ii * 256;
            if (i < 1024) {
                int part = i >> 9, rr = (i >> 2) & 127, cc = i & 3;
                const __nv_bfloat16* src = (part ? Al : Ah) + (m0 + rr) * 768 + k0 + cc * 8;
                cp_async16(st + part * APB + rr * 80 + cc * 16, src);
            } else {
                int j = i - 1024;
                int part = j >= 384; int jj = j - (part ? 384 : 0);
                int rr = jj >> 2, cc = jj & 3;
                const __nv_bfloat16* src = (part ? Bl : Bh) + (size_t)(n0 + rr) * 768 + k0 + cc * 8;
                cp_async16(st + 2 * APB + part * BPB + rr * 80 + cc * 16, src);
            }
        }
        cp_commit();
    };

    fill(0, 0);
    for (int c = 0; c < 24; c++) {
        if (c < 23) { fill((c + 1) & 1, c + 1); cp_wait1(); } else { cp_wait0(); }
        __syncthreads();

        uint32_t st = sbase + (c & 1) * STG;
#pragma unroll
        for (int step = 0; step < 2; step++) {
            uint32_t ab = st + (wm * 32 + a_lr) * 80 + (step * 16 + a_lc) * 2;
            uint32_t bb = st + 2 * APB + (wn * 48 + b_ln) * 80 + (step * 16 + b_lk) * 2;
            uint32_t Af[2][4], Alf[2][4], Bf[3][4], Blf[3][4];
            ldsm4(Af[0], ab);           ldsm4(Af[1], ab + 1280);
            ldsm4(Alf[0], ab + APB);    ldsm4(Alf[1], ab + APB + 1280);
#pragma unroll
            for (int ng = 0; ng < 3; ng++) {
                ldsm4(Bf[ng],  bb + ng * 1280);
                ldsm4(Blf[ng], bb + BPB + ng * 1280);
            }
#pragma unroll
            for (int mi = 0; mi < 2; mi++)
#pragma unroll
                for (int ng = 0; ng < 3; ng++) {
                    mma16816(acc[mi][ng * 2 + 0], Af[mi],  Bf[ng][0],  Bf[ng][1]);
                    mma16816(acc[mi][ng * 2 + 0], Af[mi],  Blf[ng][0], Blf[ng][1]);
                    mma16816(acc[mi][ng * 2 + 0], Alf[mi], Bf[ng][0],  Bf[ng][1]);
                    mma16816(acc[mi][ng * 2 + 1], Af[mi],  Bf[ng][2],  Bf[ng][3]);
                    mma16816(acc[mi][ng * 2 + 1], Af[mi],  Blf[ng][2], Blf[ng][3]);
                    mma16816(acc[mi][ng * 2 + 1], Alf[mi], Bf[ng][2],  Bf[ng][3]);
                }
        }
        __syncthreads();
    }

    float* S = (float*)dsm;
#pragma unroll
    for (int mi = 0; mi < 2; mi++)
#pragma unroll
        for (int nj = 0; nj < 6; nj++) {
            int row = wm * 32 + mi * 16 + (lane >> 2);
            int col = wn * 48 + nj * 8 + (lane & 3) * 2;
            S[row * S_ST + col]             = acc[mi][nj][0];
            S[row * S_ST + col + 1]         = acc[mi][nj][1];
            S[(row + 8) * S_ST + col]       = acc[mi][nj][2];
            S[(row + 8) * S_ST + col + 1]   = acc[mi][nj][3];
        }
    __syncthreads();

    if (mode == 0) {
        int hh = bx >> 1;
        int dbase = (bx & 1) * 32;
        int bi = (int)(m0 >> 12);
        int nn0 = (int)(m0 & 4095);
        size_t ob = ((size_t)(bi * 12 + hh) * 4096 + nn0) * 64 + dbase;
        for (int task = wid; task < 384; task += 8) {
            int mm = task / 3;
            int which = task - 3 * mm;
            float v = S[mm * S_ST + 3 * lane + which];
            size_t o = ob + (size_t)mm * 64 + lane;
            if (which == 0) g_q[o] = v;
            else {
                __nv_bfloat16 hv, lv; split2(v, hv, lv);
                if (which == 1) { g_k_hi[o] = hv; g_k_lo[o] = lv; }
                else            { g_v_hi[o] = hv; g_v_lo[o] = lv; }
            }
        }
    } else if (mode == 1) {
        for (int task = wid; task < 384; task += 8) {
            int mm = task / 3;
            int g = task - 3 * mm;
            int cgl = n0 + g * 32 + lane;
            int hh = cgl >> 6, d = cgl & 63;
            int r = (int)m0 + mm;
            if (r < 1023) {
                __nv_bfloat16 hv, lv; split2(S[mm * S_ST + g * 32 + lane], hv, lv);
                size_t o = ((size_t)hh * 1023 + r) * 64 + d;
                g_relk_hi[o] = hv; g_relk_lo[o] = lv;
            }
        }
    } else {
        for (int task = wid; task < 384; task += 8) {
            int mm = task / 3;
            int g = task - 3 * mm;
            int j = g * 32 + lane;
            Cout[(m0 + mm) * 768 + n0 + j] = S[mm * S_ST + j] + bias[n0 + j];
        }
    }
}

// merged QKV (1536 blocks) + relk (64 blocks), 1D grid of 1600
__global__ __launch_bounds__(256, 2) void mma_gemm_merged() {
    int bid = blockIdx.x;
    if (bid < 1536)
        mma_gemm_body(bid % 24, bid / 24, g_x_hi, g_x_lo, g_wqkv_hi, g_wqkv_lo,
                      nullptr, nullptr, 0);
    else {
        int rid = bid - 1536;
        mma_gemm_body(rid % 8, rid / 8, g_pos_hi, g_pos_lo, g_wrel_hi, g_wrel_lo,
                      nullptr, nullptr, 1);
    }
}

// out-proj
__global__ __launch_bounds__(256, 2) void mma_gemm_out(const float* __restrict__ bias,
                                                       float* __restrict__ Cout) {
    mma_gemm_body(blockIdx.x, blockIdx.y, g_att_hi, g_att_lo, g_wout_hi, g_wout_lo,
                  bias, Cout, 2);
}

// ================= kernel 3: tensor-core fused window attention =================
// 25 chunks: 8 K, 9 rel, 8 V. 3-stage ring, one sync per chunk.
// At c==17: fill(19) FIRST (buffer freed by compute(16)), then softmax.
#define OFF_QCH 132096
#define OFF_KV  168960
#define OFF_RS  224256
#define ATT_SMEM 224512

__global__ __launch_bounds__(256) void attn_kernel(const float* __restrict__ rcb,
                                                   const float* __restrict__ rpb)
{
    extern __shared__ char smb[];
    float* S = (float*)smb;
    float* rs = (float*)(smb + OFF_RS);
    uint32_t sb = smem_u32(smb);
    int tid = threadIdx.x, wid = tid >> 5, lane = tid & 31;
    int wm = wid & 1, wn = wid >> 1;

    int tt = blockIdx.x & 7, win = blockIdx.x >> 3;
    int bN = win / 96, rem = win - bN * 96, h = rem >> 3, w = rem & 7;
    int t0 = tt << 6;
    size_t base = ((size_t)(bN * 12 + h)) * 4096 + (size_t)w * 512;
    const float* qb = g_q + (base + t0) * 64;
    const __nv_bfloat16 *kh = g_k_hi + base * 64, *klp = g_k_lo + base * 64;
    const __nv_bfloat16 *vh = g_v_hi + base * 64, *vlp = g_v_lo + base * 64;
    const __nv_bfloat16 *rh = g_relk_hi + (size_t)h * 1023 * 64;
    const __nv_bfloat16 *rlp = g_relk_lo + (size_t)h * 1023 * 64;
    int rbase = 448 - t0;

    auto fillChunk = [&](int ch) {
        int st = ch % 3;
        const __nv_bfloat16 *ph, *pl;
        int row0, rowmax;
        if (ch < 8)       { ph = kh; pl = klp; row0 = ch * 64; rowmax = 511; }
        else if (ch < 17) { ph = rh; pl = rlp; row0 = rbase + (ch - 8) * 64; rowmax = 1022; }
        else              { ph = vh; pl = vlp; row0 = (ch - 17) * 64; rowmax = 511; }
#pragma unroll
        for (int t = 0; t < 4; t++) {
            int i = tid + t * 256;
            int part = i >> 9, r = (i >> 3) & 63, cc = i & 7;
            int rr = row0 + r; if (rr > rowmax) rr = rowmax;
            const __nv_bfloat16* src = (part ? pl : ph) + (size_t)rr * 64 + cc * 8;
            cp_async16(sb + OFF_KV + st * 18432 + part * 9216 + r * 144 + cc * 16, src);
        }
        cp_commit();
    };

    fillChunk(0);
    fillChunk(1);

    // q prep: +bias (fp32), split -> qc hi/lo, qp hi/lo (stride 144B)
    {
        int r = tid >> 2, c0 = (tid & 3) << 4;
#pragma unroll
        for (int i = 0; i < 4; i++) {
            int cc = c0 + i * 4;
            float4 qv = *(const float4*)(qb + r * 64 + cc);
            float4 bc = *(const float4*)(rcb + h * 64 + cc);
            float4 bp = *(const float4*)(rpb + h * 64 + cc);
            uint32_t off = r * 144 + cc * 2;
            uint32_t lo, hi;
            hi = pack_split(qv.x + bc.x, qv.y + bc.y, lo);
            *(uint32_t*)(smb + OFF_QCH + off) = hi;        *(uint32_t*)(smb + OFF_QCH + 9216 + off) = lo;
            hi = pack_split(qv.z + bc.z, qv.w + bc.w, lo);
            *(uint32_t*)(smb + OFF_QCH + off + 4) = hi;    *(uint32_t*)(smb + OFF_QCH + 9216 + off + 4) = lo;
            hi = pack_split(qv.x + bp.x, qv.y + bp.y, lo);
            *(uint32_t*)(smb + OFF_QCH + 18432 + off) = hi;   *(uint32_t*)(smb + OFF_QCH + 27648 + off) = lo;
            hi = pack_split(qv.z + bp.z, qv.w + bp.w, lo);
            *(uint32_t*)(smb + OFF_QCH + 18432 + off + 4) = hi; *(uint32_t*)(smb + OFF_QCH + 27648 + off + 4) = lo;
        }
    }

    float o[2][2][4];
#pragma unroll
    for (int a = 0; a < 2; a++)
#pragma unroll
        for (int bq = 0; bq < 2; bq++)
#pragma unroll
            for (int q = 0; q < 4; q++) o[a][bq][q] = 0.f;

    for (int c = 0; c < 25; c++) {
        if (c < 24) cp_wait1(); else cp_wait0();
        __syncthreads();

        if (c <= 22) fillChunk(c + 2);   // issue loads before softmax work

        if (c == 17) {
            // softmax + in-place P bf16 hi/lo conversion (blocked 32B layout)
            int r = tid >> 2, l4 = tid & 3;
            float* Sr = S + r * 516;
            float mx = -3.0e38f;
            for (int bq = l4; bq < 64; bq += 4) {
                float4 v0 = *(float4*)&Sr[bq * 8];
                float4 v1 = *(float4*)&Sr[bq * 8 + 4];
                mx = fmaxf(mx, fmaxf(fmaxf(v0.x, v0.y), fmaxf(v0.z, v0.w)));
                mx = fmaxf(mx, fmaxf(fmaxf(v1.x, v1.y), fmaxf(v1.z, v1.w)));
            }
            mx = fmaxf(mx, __shfl_xor_sync(0xffffffffu, mx, 1));
            mx = fmaxf(mx, __shfl_xor_sync(0xffffffffu, mx, 2));
            float sum = 0.f;
            for (int bq = l4; bq < 64; bq += 4) {
                float4 v0 = *(float4*)&Sr[bq * 8];
                float4 v1 = *(float4*)&Sr[bq * 8 + 4];
                float e0 = __expf(v0.x - mx), e1 = __expf(v0.y - mx);
                float e2 = __expf(v0.z - mx), e3 = __expf(v0.w - mx);
                float e4 = __expf(v1.x - mx), e5 = __expf(v1.y - mx);
                float e6 = __expf(v1.z - mx), e7 = __expf(v1.w - mx);
                sum += (e0 + e1 + e2 + e3) + (e4 + e5 + e6 + e7);
                uint32_t l0, l1, l2, l3;
                uint32_t h0 = pack_split(e0, e1, l0);
                uint32_t h1 = pack_split(e2, e3, l1);
                uint32_t h2 = pack_split(e4, e5, l2);
                uint32_t h3 = pack_split(e6, e7, l3);
                uint4 hv; hv.x = h0; hv.y = h1; hv.z = h2; hv.w = h3;
                uint4 lv; lv.x = l0; lv.y = l1; lv.z = l2; lv.w = l3;
                *(uint4*)((char*)Sr + bq * 32) = hv;
                *(uint4*)((char*)Sr + bq * 32 + 16) = lv;
            }
            sum += __shfl_xor_sync(0xffffffffu, sum, 1);
            sum += __shfl_xor_sync(0xffffffffu, sum, 2);
            if (l4 == 0) rs[r] = sum;
            __syncthreads();
        }

        uint32_t kvh = sb + OFF_KV + (c % 3) * 18432;
        uint32_t kvl = kvh + 9216;

        if (c < 17) {
            bool isRel = c >= 8;
            uint32_t qh = sb + OFF_QCH + (isRel ? 18432 : 0);
            uint32_t ql = qh + 9216;
            float acc[2][2][4];
#pragma unroll
            for (int a = 0; a < 2; a++)
#pragma unroll
                for (int bq = 0; bq < 2; bq++)
#pragma unroll
                    for (int q = 0; q < 4; q++) acc[a][bq][q] = 0.f;
#pragma unroll
            for (int ks = 0; ks < 4; ks++) {
                uint32_t aoff = (32 * wm + (lane & 15)) * 144 + ks * 32 + ((lane >> 4) << 4);
                uint32_t Ah0[4], Ah1[4], Al0[4], Al1[4], Bh[4], Bl[4];
                ldsm4(Ah0, qh + aoff); ldsm4(Ah1, qh + aoff + 2304);
                ldsm4(Al0, ql + aoff); ldsm4(Al1, ql + aoff + 2304);
                uint32_t boff = (16 * wn + ((lane >> 4) << 3) + (lane & 7)) * 144
                              + ks * 32 + ((lane & 8) << 1);
                ldsm4(Bh, kvh + boff); ldsm4(Bl, kvl + boff);
                mma16816(acc[0][0], Ah0, Bh[0], Bh[1]); mma16816(acc[0][1], Ah0, Bh[2], Bh[3]);
                mma16816(acc[1][0], Ah1, Bh[0], Bh[1]); mma16816(acc[1][1], Ah1, Bh[2], Bh[3]);
                mma16816(acc[0][0], Ah0, Bl[0], Bl[1]); mma16816(acc[0][1], Ah0, Bl[2], Bl[3]);
                mma16816(acc[1][0], Ah1, Bl[0], Bl[1]); mma16816(acc[1][1], Ah1, Bl[2], Bl[3]);
                mma16816(acc[0][0], Al0, Bh[0], Bh[1]); mma16816(acc[0][1], Al0, Bh[2], Bh[3]);
                mma16816(acc[1][0], Al1, Bh[0], Bh[1]); mma16816(acc[1][1], Al1, Bh[2], Bh[3]);
            }
            if (!isRel) {
                int scol = c * 64 + 16 * wn;
#pragma unroll
                for (int mt = 0; mt < 2; mt++) {
                    int t1 = 32 * wm + 16 * mt + (lane >> 2);
#pragma unroll
                    for (int nt = 0; nt < 2; nt++) {
                        int col = scol + 8 * nt + ((lane & 3) << 1);
                        S[t1 * 516 + col]           = acc[mt][nt][0] * 0.125f;
                        S[t1 * 516 + col + 1]       = acc[mt][nt][1] * 0.125f;
                        S[(t1 + 8) * 516 + col]     = acc[mt][nt][2] * 0.125f;
                        S[(t1 + 8) * 516 + col + 1] = acc[mt][nt][3] * 0.125f;
                    }
                }
            } else {
                int colb = (c - 8) * 64 + 16 * wn;
#pragma unroll
                for (int mt = 0; mt < 2; mt++) {
                    int t1 = 32 * wm + 16 * mt + (lane >> 2);
#pragma unroll
                    for (int nt = 0; nt < 2; nt++) {
                        int rl0 = colb + 8 * nt + ((lane & 3) << 1);
                        int s1 = rl0 + t1 - 63;
                        if (s1 >= 0 && s1 < 512)         S[t1 * 516 + s1]           += acc[mt][nt][0];
                        if (s1 + 1 >= 0 && s1 + 1 < 512) S[t1 * 516 + s1 + 1]       += acc[mt][nt][1];
                        int s2 = s1 + 8;
                        if (s2 >= 0 && s2 < 512)         S[(t1 + 8) * 516 + s2]     += acc[mt][nt][2];
                        if (s2 + 1 >= 0 && s2 + 1 < 512) S[(t1 + 8) * 516 + s2 + 1] += acc[mt][nt][3];
                    }
                }
            }
        } else {
            int cv = c - 17;
#pragma unroll
            for (int ks = 0; ks < 4; ks++) {
                uint32_t aoff = (32 * wm + (lane & 15)) * 2064 + cv * 256 + ks * 64
                              + ((lane >> 4) << 5);
                uint32_t Ph0[4], Ph1[4], Pl0[4], Pl1[4], Vh[4], Vl[4];
                ldsm4(Ph0, sb + aoff); ldsm4(Ph1, sb + aoff + 33024);
                ldsm4(Pl0, sb + aoff + 16); ldsm4(Pl1, sb + aoff + 33024 + 16);
                int g = lane >> 3;
                uint32_t boff = (ks * 16 + ((g & 1) << 3) + (lane & 7)) * 144
                              + 32 * wn + ((g >> 1) << 4);
                ldsm4t(Vh, kvh + boff); ldsm4t(Vl, kvl + boff);
                mma16816(o[0][0], Ph0, Vh[0], Vh[1]); mma16816(o[0][1], Ph0, Vh[2], Vh[3]);
                mma16816(o[1][0], Ph1, Vh[0], Vh[1]); mma16816(o[1][1], Ph1, Vh[2], Vh[3]);
                mma16816(o[0][0], Ph0, Vl[0], Vl[1]); mma16816(o[0][1], Ph0, Vl[2], Vl[3]);
                mma16816(o[1][0], Ph1, Vl[0], Vl[1]); mma16816(o[1][1], Ph1, Vl[2], Vl[3]);
                mma16816(o[0][0], Pl0, Vh[0], Vh[1]); mma16816(o[0][1], Pl0, Vh[2], Vh[3]);
                mma16816(o[1][0], Pl1, Vh[0], Vh[1]); mma16816(o[1][1], Pl1, Vh[2], Vh[3]);
            }
        }
    }

    // normalize + write bf16 hi/lo for out-proj
    int colc = 16 * wn;
#pragma unroll
    for (int mt = 0; mt < 2; mt++) {
        int t1 = 32 * wm + 16 * mt + (lane >> 2);
        float i1 = 1.f / rs[t1], i2 = 1.f / rs[t1 + 8];
        size_t row1 = (size_t)bN * 4096 + (size_t)w * 512 + t0 + t1;
#pragma unroll
        for (int nt = 0; nt < 2; nt++) {
            int col = colc + 8 * nt + ((lane & 3) << 1);
            size_t off1 = row1 * 768 + h * 64 + col;
            size_t off2 = (row1 + 8) * 768 + h * 64 + col;
            uint32_t lo, hi;
            hi = pack_split(o[mt][nt][0] * i1, o[mt][nt][1] * i1, lo);
            *(uint32_t*)(g_att_hi + off1) = hi;
            *(uint32_t*)(g_att_lo + off1) = lo;
            hi = pack_split(o[mt][nt][2] * i2, o[mt][nt][3] * i2, lo);
            *(uint32_t*)(g_att_hi + off2) = hi;
            *(uint32_t*)(g_att_lo + off2) = lo;
        }
    }
}

// ================= launch =================
extern "C" void kernel_launch(void* const* d_in, const int* in_sizes, int n_in,
                              void* d_out, int out_size)
{
    const float* x     = (const float*)d_in[0];
    const float* w_qkv = (const float*)d_in[1];
    const float* w_out = (const float*)d_in[2];
    const float* b_out = (const float*)d_in[3];
    const float* w_rel = (const float*)d_in[4];
    const float* rcb   = (const float*)d_in[5];
    const float* rpb   = (const float*)d_in[6];
    float* out = (float*)d_out;

    cudaFuncSetAttribute(attn_kernel, cudaFuncAttributeMaxDynamicSharedMemorySize, ATT_SMEM);
    cudaFuncSetAttribute(mma_gemm_merged, cudaFuncAttributeMaxDynamicSharedMemorySize, GEMM_SMEM);
    cudaFuncSetAttribute(mma_gemm_out, cudaFuncAttributeMaxDynamicSharedMemorySize, GEMM_SMEM);

    // 1. all prologue work (x split, 3 weight splits, positional embed) in one launch
    prep_kernel<<<5440, 256>>>(x, w_qkv, w_out, w_rel);
    // 2. QKV projection + relk projection merged (relk fills QKV tail wave)
    mma_gemm_merged<<<1600, 256, GEMM_SMEM>>>();
    // 3. fused attention
    attn_kernel<<<1536, 256, ATT_SMEM>>>(rcb, rpb);
    // 4. output projection
    mma_gemm_out<<<dim3(8, 64), 256, GEMM_SMEM>>>(b_out, out);
}